// round 12
// baseline (speedup 1.0000x reference)
#include <cuda_runtime.h>
#include <cuda_bf16.h>
#include <math.h>
#include <stdint.h>
#include <stddef.h>

// Problem constants
#define TT 256
#define BB 64
#define HH 1024
#define IN3H 3072          // 3*H
#define INK 2048           // input width of every layer (IN = 2H)
#define GX_M (TT * BB)     // 16384
#define GXSZ ((size_t)GX_M * IN3H)

#define REC_BLOCKS 144     // 2 dirs * 24 N-tiles(128) * 3 K-splits
#define REC_THREADS 256

// ---------------------------------------------------------------------------
// Scratch (device globals -- no allocation allowed)
// ---------------------------------------------------------------------------
__device__ float g_gx[2 * GXSZ];                        // input gates (fp32)
__device__ float g_ghp[3][2][(size_t)BB * IN3H];        // hidden-gate partials
__device__ __nv_bfloat16 g_hhi[2 * BB * HH];            // hidden state hi/lo
__device__ __nv_bfloat16 g_hlo[2 * BB * HH];
__device__ __nv_bfloat16 g_ahi[(size_t)GX_M * INK];     // layer input hi/lo
__device__ __nv_bfloat16 g_alo[(size_t)GX_M * INK];
__device__ __nv_bfloat16 g_whi[(size_t)6 * IN3H * INK]; // w_ih hi/lo
__device__ __nv_bfloat16 g_wlo[(size_t)6 * IN3H * INK];
__device__ __nv_bfloat16 g_uhi[(size_t)6 * IN3H * HH];  // w_hh hi/lo
__device__ __nv_bfloat16 g_ulo[(size_t)6 * IN3H * HH];

__device__ unsigned g_bar_count = 0;
__device__ unsigned g_bar_phase = 0;

// ---------------------------------------------------------------------------
// Baseline-PTX helpers (valid on compute_103)
// ---------------------------------------------------------------------------
__device__ __forceinline__ uint32_t smem_u32(const void* p) {
    uint32_t a;
    asm("{ .reg .u64 t; cvta.to.shared.u64 t, %1; cvt.u32.u64 %0, t; }"
        : "=r"(a) : "l"(p));
    return a;
}

__device__ __forceinline__ void cp_async16(uint32_t dst, const void* src) {
    asm volatile("cp.async.cg.shared.global [%0], [%1], 16;"
                 :: "r"(dst), "l"(src) : "memory");
}
#define CP_COMMIT() asm volatile("cp.async.commit_group;" ::: "memory")
#define CP_WAIT0()  asm volatile("cp.async.wait_group 0;" ::: "memory")
#define CP_WAIT1()  asm volatile("cp.async.wait_group 1;" ::: "memory")

__device__ __forceinline__ void ldsm4(uint32_t* r, uint32_t addr) {
    asm volatile("ldmatrix.sync.aligned.m8n8.x4.shared.b16 {%0,%1,%2,%3}, [%4];"
                 : "=r"(r[0]), "=r"(r[1]), "=r"(r[2]), "=r"(r[3]) : "r"(addr));
}

__device__ __forceinline__ void mma_bf16(float* c, const uint32_t* a,
                                         uint32_t b0, uint32_t b1) {
    asm("mma.sync.aligned.m16n8k16.row.col.f32.bf16.bf16.f32 "
        "{%0,%1,%2,%3}, {%4,%5,%6,%7}, {%8,%9}, {%0,%1,%2,%3};"
        : "+f"(c[0]), "+f"(c[1]), "+f"(c[2]), "+f"(c[3])
        : "r"(a[0]), "r"(a[1]), "r"(a[2]), "r"(a[3]), "r"(b0), "r"(b1));
}

__device__ __forceinline__ void prefetch_l2(const void* p) {
    asm volatile("prefetch.global.L2 [%0];" :: "l"(p));
}

// ---------------------------------------------------------------------------
// Split fp32 -> (bf16 hi, bf16 lo)
// ---------------------------------------------------------------------------
__device__ __forceinline__ uint32_t pack2bf(float a, float b) {
    __nv_bfloat162 t = __floats2bfloat162_rn(a, b);
    return *(uint32_t*)&t;
}

__global__ __launch_bounds__(256) void split_bf16_kernel(
    const float* __restrict__ src, __nv_bfloat16* __restrict__ hi,
    __nv_bfloat16* __restrict__ lo, size_t n4) {
    size_t i = (size_t)blockIdx.x * 256 + threadIdx.x;
    if (i >= n4) return;
    float4 v = ((const float4*)src)[i];
    float h0 = __bfloat162float(__float2bfloat16(v.x));
    float h1 = __bfloat162float(__float2bfloat16(v.y));
    float h2 = __bfloat162float(__float2bfloat16(v.z));
    float h3 = __bfloat162float(__float2bfloat16(v.w));
    uint2 hv, lv;
    hv.x = pack2bf(v.x, v.y);           hv.y = pack2bf(v.z, v.w);
    lv.x = pack2bf(v.x - h0, v.y - h1); lv.y = pack2bf(v.z - h2, v.w - h3);
    ((uint2*)hi)[i] = hv;
    ((uint2*)lo)[i] = lv;
}

// ---------------------------------------------------------------------------
// gx GEMM: R6 structure + R12 L2 prefetch of cp.async sources (distance 6).
// 128x128 tile, k-chunk 32, 2-stage cp.async, 2 CTAs/SM.
// ---------------------------------------------------------------------------
#define GX_STAGE 40960
#define GX_SMEM  (2 * GX_STAGE)
#define GX_NCHUNK 64
#define GX_PFD 6            // prefetch distance in chunks

__device__ __forceinline__ void gx_load(uint32_t sm, int bm, int bn, int k0,
                                        int tid, const __nv_bfloat16* Bhi,
                                        const __nv_bfloat16* Blo) {
#pragma unroll
    for (int half = 0; half < 2; half++) {
        int idx = half * 256 + tid;      // 0..511
        int r   = idx >> 2;
        int co  = k0 + (idx & 3) * 8;
        uint32_t dst = sm + r * 80 + (idx & 3) * 16;
        cp_async16(dst,          g_ahi + (size_t)(bm + r) * INK + co);
        cp_async16(dst + 10240,  g_alo + (size_t)(bm + r) * INK + co);
        cp_async16(dst + 20480,  Bhi   + (size_t)(bn + r) * INK + co);
        cp_async16(dst + 30720,  Blo   + (size_t)(bn + r) * INK + co);
    }
}

__global__ __launch_bounds__(256, 2) void gx_mma_kernel(
    const __nv_bfloat16* __restrict__ Whi,
    const __nv_bfloat16* __restrict__ Wlo,
    const float* __restrict__ bias)
{
    extern __shared__ char smem[];
    const uint32_t sb = smem_u32(smem);
    const int tid = threadIdx.x, wid = tid >> 5, lid = tid & 31;
    const int bn = blockIdx.x * 128;
    const int bm = blockIdx.y * 128;
    const int d  = blockIdx.z;

    const __nv_bfloat16* Bhi = Whi + (size_t)d * IN3H * INK;
    const __nv_bfloat16* Blo = Wlo + (size_t)d * IN3H * INK;
    const float* bptr = bias + d * IN3H;
    float* C = g_gx + (size_t)d * GXSZ;

    const uint32_t aoff = (uint32_t)(((wid & 3) * 32 + (lid & 7) + ((lid >> 3) & 1) * 8) * 80
                                     + ((lid >> 4) & 1) * 16);
    const uint32_t boff = (uint32_t)(((wid >> 2) * 64 + (lid & 7) + ((lid >> 4) & 1) * 8) * 80
                                     + ((lid >> 3) & 1) * 16);

    float acc[2][8][4];
#pragma unroll
    for (int i = 0; i < 2; i++)
#pragma unroll
        for (int j = 0; j < 8; j++)
#pragma unroll
            for (int q = 0; q < 4; q++) acc[i][j][q] = 0.f;

    // Warm L2 for the first GX_PFD chunks
    for (int cp = 0; cp < GX_PFD; cp++) {
#pragma unroll
        for (int h2 = 0; h2 < 2; h2++) {
            int idx = h2 * 256 + tid;    // 0..511
            int m   = idx >> 7;          // 0..3 (matrix select)
            int r   = idx & 127;
            const char* p;
            if (m == 0)      p = (const char*)(g_ahi + (size_t)(bm + r) * INK) + cp * 64;
            else if (m == 1) p = (const char*)(g_alo + (size_t)(bm + r) * INK) + cp * 64;
            else if (m == 2) p = (const char*)(Bhi   + (size_t)(bn + r) * INK) + cp * 64;
            else             p = (const char*)(Blo   + (size_t)(bn + r) * INK) + cp * 64;
            prefetch_l2(p);
        }
    }

    gx_load(sb, bm, bn, 0, tid, Bhi, Blo); CP_COMMIT();

    for (int c = 0; c < GX_NCHUNK; c++) {
        if (c + 1 < GX_NCHUNK) {
            gx_load(sb + ((c + 1) & 1) * GX_STAGE, bm, bn, (c + 1) * 32, tid, Bhi, Blo);
            CP_COMMIT();
            CP_WAIT1();
        } else {
            CP_WAIT0();
        }
        // Prefetch chunk c+GX_PFD into L2 (keeps cp.async on the L2-hit path)
        if (c + GX_PFD < GX_NCHUNK) {
            const int kb = (c + GX_PFD) * 64;
#pragma unroll
            for (int h2 = 0; h2 < 2; h2++) {
                int idx = h2 * 256 + tid;
                int m   = idx >> 7;
                int r   = idx & 127;
                const char* p;
                if (m == 0)      p = (const char*)(g_ahi + (size_t)(bm + r) * INK) + kb;
                else if (m == 1) p = (const char*)(g_alo + (size_t)(bm + r) * INK) + kb;
                else if (m == 2) p = (const char*)(Bhi   + (size_t)(bn + r) * INK) + kb;
                else             p = (const char*)(Blo   + (size_t)(bn + r) * INK) + kb;
                prefetch_l2(p);
            }
        }
        __syncthreads();
        const uint32_t st = sb + (c & 1) * GX_STAGE;

#pragma unroll
        for (int kk = 0; kk < 2; kk++) {
            const uint32_t ko = kk * 32;
            uint32_t ah[2][4], al[2][4];
            ldsm4(ah[0], st + aoff + ko);
            ldsm4(ah[1], st + aoff + 1280 + ko);
            ldsm4(al[0], st + 10240 + aoff + ko);
            ldsm4(al[1], st + 10240 + aoff + 1280 + ko);
#pragma unroll
            for (int g = 0; g < 4; g++) {
                uint32_t bh[4], bl[4];
                ldsm4(bh, st + 20480 + boff + g * 1280 + ko);
                ldsm4(bl, st + 30720 + boff + g * 1280 + ko);
                mma_bf16(acc[0][2 * g],     ah[0], bh[0], bh[1]);
                mma_bf16(acc[0][2 * g + 1], ah[0], bh[2], bh[3]);
                mma_bf16(acc[1][2 * g],     ah[1], bh[0], bh[1]);
                mma_bf16(acc[1][2 * g + 1], ah[1], bh[2], bh[3]);
                mma_bf16(acc[0][2 * g],     ah[0], bl[0], bl[1]);
                mma_bf16(acc[0][2 * g + 1], ah[0], bl[2], bl[3]);
                mma_bf16(acc[1][2 * g],     ah[1], bl[0], bl[1]);
                mma_bf16(acc[1][2 * g + 1], ah[1], bl[2], bl[3]);
                mma_bf16(acc[0][2 * g],     al[0], bh[0], bh[1]);
                mma_bf16(acc[0][2 * g + 1], al[0], bh[2], bh[3]);
                mma_bf16(acc[1][2 * g],     al[1], bh[0], bh[1]);
                mma_bf16(acc[1][2 * g + 1], al[1], bh[2], bh[3]);
            }
        }
        __syncthreads();
    }

    const int lr = lid >> 2;
    const int lc = (lid & 3) * 2;
#pragma unroll
    for (int mt = 0; mt < 2; mt++) {
        const int row = bm + (wid & 3) * 32 + mt * 16 + lr;
#pragma unroll
        for (int nt = 0; nt < 8; nt++) {
            const int col = bn + (wid >> 2) * 64 + nt * 8 + lc;
            float b0 = bptr[col], b1 = bptr[col + 1];
            float* c = acc[mt][nt];
            C[(size_t)row * IN3H + col]           = c[0] + b0;
            C[(size_t)row * IN3H + col + 1]       = c[1] + b1;
            C[(size_t)(row + 8) * IN3H + col]     = c[2] + b0;
            C[(size_t)(row + 8) * IN3H + col + 1] = c[3] + b1;
        }
    }
}

// ---------------------------------------------------------------------------
// Grid-wide barrier (spin, monotonic phase) -- proven R6
// ---------------------------------------------------------------------------
__device__ __forceinline__ void grid_sync(unsigned& local_phase) {
    __threadfence();
    __syncthreads();
    if (threadIdx.x == 0) {
        unsigned ph = local_phase;
        if (atomicAdd(&g_bar_count, 1u) == REC_BLOCKS - 1) {
            g_bar_count = 0;
            __threadfence();
            atomicAdd(&g_bar_phase, 1u);
        } else {
            while (*(volatile unsigned*)&g_bar_phase == ph) { }
        }
        __threadfence();
    }
    __syncthreads();
    local_phase++;
}

// ---------------------------------------------------------------------------
// Persistent recurrent kernel -- R11 structure; R12 keeps the gate-phase
// hidden state in REGISTERS across all 256 steps (mapping is step-invariant),
// removing the g_h load/store round trip from the gate critical path.
// 144 blocks = 2 dirs x 24 N-tiles(128) x 3 K-splits ({352,352,320}).
// smem map (dynamic, 200704 B):
//   A stages: [2][ hi 5120 | lo 5120 ]                   @ 0      (20480)
//   B hi:     [chunk][128 rows][64 B, XOR-swizzled]      @ 20480  (90112)
//   B lo:                                                @ 110592 (90112)
// ---------------------------------------------------------------------------
#define RC_SB_BHI 20480
#define RC_SB_BLO 110592
#define RC_SMEM   200704

__global__ __launch_bounds__(REC_THREADS)
void gru_recurrent_kernel(const float* __restrict__ h0_layer,    // [2,B,H]
                          const __nv_bfloat16* __restrict__ Uhi, // [2,3H,H]
                          const __nv_bfloat16* __restrict__ Ulo,
                          const float* __restrict__ bhh_layer,   // [2,3H]
                          float* __restrict__ hn_out)            // [2,B,H]
{
    extern __shared__ char smem[];
    const uint32_t sb = smem_u32(smem);
    const int bid = blockIdx.x, tid = threadIdx.x;
    const int wid = tid >> 5, lid = tid & 31;
    const int d   = bid / 72;
    const int rem = bid % 72;
    const int nt  = rem / 3;            // 0..23 -> 128 gh columns each
    const int ks  = rem % 3;            // K split
    const int bn0  = nt * 128;
    const int kbeg = ks * 352;          // {0, 352, 704}
    const int nc   = (ks == 2) ? 10 : 11;   // chunks of 32 k

    const __nv_bfloat16* Whi = Uhi + (size_t)d * IN3H * HH;
    const __nv_bfloat16* Wlo = Ulo + (size_t)d * IN3H * HH;
    float* Pout = g_ghp[ks][d];

    unsigned phase = *(volatile unsigned*)&g_bar_phase;
    __syncthreads();

    // ---- One-time weight preload into resident smem (swizzled 64B rows) ----
    for (int idx = tid; idx < nc * 512; idx += REC_THREADS) {
        int chunk = idx >> 9;
        int r     = (idx >> 2) & 127;
        int seg   = idx & 3;
        int col   = kbeg + chunk * 32 + seg * 8;
        uint32_t dst = (uint32_t)(chunk * 8192 + r * 64
                                  + ((seg ^ ((r >> 1) & 3)) * 16));
        cp_async16(sb + RC_SB_BHI + dst, Whi + (size_t)(bn0 + r) * HH + col);
        cp_async16(sb + RC_SB_BLO + dst, Wlo + (size_t)(bn0 + r) * HH + col);
    }
    CP_COMMIT();
    CP_WAIT0();

    // Prologue: split h0 into bf16 hi/lo state buffers
    for (int i = bid * REC_THREADS + tid; i < 2 * BB * HH;
         i += REC_BLOCKS * REC_THREADS) {
        float v = h0_layer[i];
        __nv_bfloat16 hi = __float2bfloat16(v);
        g_hhi[i] = hi;
        g_hlo[i] = __float2bfloat16(v - __bfloat162float(hi));
    }

    // Per-thread gate-state registers: mapping p -> (d2,b,jp) is step-invariant.
    // p0 = bid*256+tid, p1 = p0 + 36864 (if < 65536).
    float2 hreg[2];
    int pidx[2], pcnt = 0;
    {
        int p = bid * REC_THREADS + tid;
#pragma unroll
        for (int q = 0; q < 2; q++) {
            if (p < 65536) {
                pidx[pcnt] = p;
                const int d2 = p >> 15;
                const int rm = p & 32767;
                const int b  = rm >> 9;
                const int jp = (rm & 511) << 1;
                const int i  = d2 * BB * HH + b * HH + jp;
                hreg[pcnt] = *(const float2*)(h0_layer + i);
                pcnt++;
            }
            p += REC_BLOCKS * REC_THREADS;
        }
    }
    grid_sync(phase);

    // A ldmatrix offsets (80B padded rows): warp m = (wid&1)*32
    const uint32_t aoff = (uint32_t)(((wid & 1) * 32 + (lid & 7) + ((lid >> 3) & 1) * 8) * 80
                                     + ((lid >> 4) & 1) * 16);
    // B ldmatrix (64B rows, XOR swizzle): warp n = (wid>>1)*32
    const int brow0 = (wid >> 1) * 32 + (lid & 7) + ((lid >> 4) & 1) * 8;
    const int bkey  = (brow0 >> 1) & 3;
    const int lb3   = (lid >> 3) & 1;
    const uint32_t bseg0 = (uint32_t)(((0 + lb3) ^ bkey) * 16);  // kk=0
    const uint32_t bseg1 = (uint32_t)(((2 + lb3) ^ bkey) * 16);  // kk=1
    const uint32_t bbase = (uint32_t)(brow0 * 64);

    const __nv_bfloat16* hhi = g_hhi + (size_t)d * BB * HH;
    const __nv_bfloat16* hlo = g_hlo + (size_t)d * BB * HH;

    const int a_r  = tid >> 2;
    const int a_sg = tid & 3;

    for (int s = 0; s < TT; s++) {
        float acc[2][4][4];
#pragma unroll
        for (int i = 0; i < 2; i++)
#pragma unroll
            for (int j = 0; j < 4; j++)
#pragma unroll
                for (int q = 0; q < 4; q++) acc[i][j][q] = 0.f;

        {   // prologue A load, chunk 0
            uint32_t dst = sb + a_r * 80 + a_sg * 16;
            const int co = kbeg + a_sg * 8;
            cp_async16(dst,        hhi + (size_t)a_r * HH + co);
            cp_async16(dst + 5120, hlo + (size_t)a_r * HH + co);
            CP_COMMIT();
        }

        // Prefetch this step's gx rows into L2 (R11 win)
        {
            const int ln = bid * REC_THREADS + tid;   // 36864 threads
            if (ln < 6144) {
                prefetch_l2(g_gx + (size_t)s * BB * IN3H + (size_t)ln * 32);
            } else if (ln < 12288) {
                prefetch_l2(g_gx + GXSZ + (size_t)(TT - 1 - s) * BB * IN3H
                            + (size_t)(ln - 6144) * 32);
            }
        }

        for (int c = 0; c < nc; c++) {
            if (c + 1 < nc) {
                uint32_t dst = sb + ((c + 1) & 1) * 10240 + a_r * 80 + a_sg * 16;
                const int co = kbeg + (c + 1) * 32 + a_sg * 8;
                cp_async16(dst,        hhi + (size_t)a_r * HH + co);
                cp_async16(dst + 5120, hlo + (size_t)a_r * HH + co);
                CP_COMMIT();
                CP_WAIT1();
            } else {
                CP_WAIT0();
            }
            __syncthreads();
            const uint32_t stA  = sb + (c & 1) * 10240;
            const uint32_t stBh = sb + RC_SB_BHI + c * 8192 + bbase;
            const uint32_t stBl = sb + RC_SB_BLO + c * 8192 + bbase;

#pragma unroll
            for (int kk = 0; kk < 2; kk++) {
                const uint32_t ko  = kk * 32;
                const uint32_t bso = kk ? bseg1 : bseg0;
                uint32_t ah[2][4], al[2][4], bh[2][4], bl[2][4];
                ldsm4(ah[0], stA + aoff + ko);
                ldsm4(ah[1], stA + aoff + 1280 + ko);
                ldsm4(al[0], stA + 5120 + aoff + ko);
                ldsm4(al[1], stA + 5120 + aoff + 1280 + ko);
                ldsm4(bh[0], stBh + bso);
                ldsm4(bh[1], stBh + 1024 + bso);   // +16 rows * 64B
                ldsm4(bl[0], stBl + bso);
                ldsm4(bl[1], stBl + 1024 + bso);
#pragma unroll
                for (int mt = 0; mt < 2; mt++)
#pragma unroll
                    for (int g = 0; g < 2; g++) {
                        mma_bf16(acc[mt][2 * g],     ah[mt], bh[g][0], bh[g][1]);
                        mma_bf16(acc[mt][2 * g + 1], ah[mt], bh[g][2], bh[g][3]);
                    }
#pragma unroll
                for (int mt = 0; mt < 2; mt++)
#pragma unroll
                    for (int g = 0; g < 2; g++) {
                        mma_bf16(acc[mt][2 * g],     ah[mt], bl[g][0], bl[g][1]);
                        mma_bf16(acc[mt][2 * g + 1], ah[mt], bl[g][2], bl[g][3]);
                    }
#pragma unroll
                for (int mt = 0; mt < 2; mt++)
#pragma unroll
                    for (int g = 0; g < 2; g++) {
                        mma_bf16(acc[mt][2 * g],     al[mt], bh[g][0], bh[g][1]);
                        mma_bf16(acc[mt][2 * g + 1], al[mt], bh[g][2], bh[g][3]);
                    }
            }
            __syncthreads();
        }

        // Epilogue: write 64x128 partial tile
        {
            const int lr = lid >> 2;
            const int lc = (lid & 3) * 2;
#pragma unroll
            for (int mt = 0; mt < 2; mt++) {
                const int row = (wid & 1) * 32 + mt * 16 + lr;
#pragma unroll
                for (int j = 0; j < 4; j++) {
                    const int col = bn0 + (wid >> 1) * 32 + j * 8 + lc;
                    float* c = acc[mt][j];
                    Pout[(size_t)row * IN3H + col]           = c[0];
                    Pout[(size_t)row * IN3H + col + 1]       = c[1];
                    Pout[(size_t)(row + 8) * IN3H + col]     = c[2];
                    Pout[(size_t)(row + 8) * IN3H + col + 1] = c[3];
                }
            }
        }

        grid_sync(phase);

        // Gate phase -- float2 vectorized; h state kept in registers
#pragma unroll
        for (int q2 = 0; q2 < 2; q2++) {
            if (q2 >= pcnt) break;
            const int p  = pidx[q2];
            const int d2 = p >> 15;
            const int rm = p & 32767;
            const int b  = rm >> 9;
            const int jp = (rm & 511) << 1;
            const int i  = d2 * BB * HH + b * HH + jp;
            const int t  = d2 ? (TT - 1 - s) : s;

            const float* gxp = g_gx + (size_t)d2 * GXSZ + ((size_t)t * BB + b) * IN3H;
            const float* P0 = g_ghp[0][d2] + (size_t)b * IN3H;
            const float* P1 = g_ghp[1][d2] + (size_t)b * IN3H;
            const float* P2 = g_ghp[2][d2] + (size_t)b * IN3H;
            const float* bias2 = bhh_layer + d2 * IN3H;

            float2 gr  = *(const float2*)(gxp + jp);
            float2 gz  = *(const float2*)(gxp + HH + jp);
            float2 gn  = *(const float2*)(gxp + 2 * HH + jp);
            float2 p0r = *(const float2*)(P0 + jp);
            float2 p0z = *(const float2*)(P0 + HH + jp);
            float2 p0n = *(const float2*)(P0 + 2 * HH + jp);
            float2 p1r = *(const float2*)(P1 + jp);
            float2 p1z = *(const float2*)(P1 + HH + jp);
            float2 p1n = *(const float2*)(P1 + 2 * HH + jp);
            float2 p2r = *(const float2*)(P2 + jp);
            float2 p2z = *(const float2*)(P2 + HH + jp);
            float2 p2n = *(const float2*)(P2 + 2 * HH + jp);
            float2 br  = *(const float2*)(bias2 + jp);
            float2 bz  = *(const float2*)(bias2 + HH + jp);
            float2 bn2 = *(const float2*)(bias2 + 2 * HH + jp);

            float hnew[2];
#pragma unroll
            for (int q = 0; q < 2; q++) {
                float ghr = (q ? p0r.y + p1r.y + p2r.y + br.y
                               : p0r.x + p1r.x + p2r.x + br.x);
                float ghz = (q ? p0z.y + p1z.y + p2z.y + bz.y
                               : p0z.x + p1z.x + p2z.x + bz.x);
                float ghn = (q ? p0n.y + p1n.y + p2n.y + bn2.y
                               : p0n.x + p1n.x + p2n.x + bn2.x);
                float gxr = q ? gr.y : gr.x;
                float gxz = q ? gz.y : gz.x;
                float gxn = q ? gn.y : gn.x;
                float hol = q ? hreg[q2].y : hreg[q2].x;

                float r = 1.f / (1.f + expf(-(gxr + ghr)));
                float z = 1.f / (1.f + expf(-(gxz + ghz)));
                float n = tanhf(gxn + r * ghn);
                hnew[q] = n + z * (hol - n);
            }

            hreg[q2] = make_float2(hnew[0], hnew[1]);

            __nv_bfloat162 h2 = __floats2bfloat162_rn(hnew[0], hnew[1]);
            float r0 = hnew[0] - __bfloat162float(__low2bfloat16(h2));
            float r1 = hnew[1] - __bfloat162float(__high2bfloat16(h2));
            __nv_bfloat162 l2v = __floats2bfloat162_rn(r0, r1);

            *(__nv_bfloat162*)(g_hhi + i) = h2;
            *(__nv_bfloat162*)(g_hlo + i) = l2v;

            size_t oidx = ((size_t)t * BB + b) * INK + (size_t)d2 * HH + jp;
            *(__nv_bfloat162*)(g_ahi + oidx) = h2;
            *(__nv_bfloat162*)(g_alo + oidx) = l2v;

            if (s == TT - 1) *(float2*)(hn_out + i) = hreg[q2];
        }

        grid_sync(phase);
    }
}

// ---------------------------------------------------------------------------
// Launch
// ---------------------------------------------------------------------------
extern "C" void kernel_launch(void* const* d_in, const int* in_sizes, int n_in,
                              void* d_out, int out_size) {
    const float* x   = (const float*)d_in[0];  // [T, B, 2048]
    const float* h0  = (const float*)d_in[1];  // [6, B, H]
    const float* wih = (const float*)d_in[2];  // [3, 2, 3072, 2048]
    const float* whh = (const float*)d_in[3];  // [3, 2, 3072, 1024]
    const float* bih = (const float*)d_in[4];  // [3, 2, 3072]
    const float* bhh = (const float*)d_in[5];  // [3, 2, 3072]
    float* out = (float*)d_out;                // [6, B, H]

    __nv_bfloat16 *ahi, *alo, *whi, *wlo, *uhi, *ulo;
    cudaGetSymbolAddress((void**)&ahi, g_ahi);
    cudaGetSymbolAddress((void**)&alo, g_alo);
    cudaGetSymbolAddress((void**)&whi, g_whi);
    cudaGetSymbolAddress((void**)&wlo, g_wlo);
    cudaGetSymbolAddress((void**)&uhi, g_uhi);
    cudaGetSymbolAddress((void**)&ulo, g_ulo);

    cudaFuncSetAttribute(gx_mma_kernel,
                         cudaFuncAttributeMaxDynamicSharedMemorySize, GX_SMEM);
    cudaFuncSetAttribute(gru_recurrent_kernel,
                         cudaFuncAttributeMaxDynamicSharedMemorySize, RC_SMEM);

    {   // split w_ih
        size_t n4 = (size_t)6 * IN3H * INK / 4;
        split_bf16_kernel<<<(unsigned)((n4 + 255) / 256), 256>>>(wih, whi, wlo, n4);
    }
    {   // split w_hh
        size_t n4 = (size_t)6 * IN3H * HH / 4;
        split_bf16_kernel<<<(unsigned)((n4 + 255) / 256), 256>>>(whh, uhi, ulo, n4);
    }
    {   // split x (layer-0 input)
        size_t n4 = (size_t)GX_M * INK / 4;
        split_bf16_kernel<<<(unsigned)((n4 + 255) / 256), 256>>>(x, ahi, alo, n4);
    }

    for (int l = 0; l < 3; l++) {
        gx_mma_kernel<<<dim3(IN3H / 128, GX_M / 128, 2), 256, GX_SMEM>>>(
            whi + (size_t)l * 2 * IN3H * INK,
            wlo + (size_t)l * 2 * IN3H * INK,
            bih + (size_t)l * 2 * IN3H);

        gru_recurrent_kernel<<<REC_BLOCKS, REC_THREADS, RC_SMEM>>>(
            h0  + (size_t)l * 2 * BB * HH,
            uhi + (size_t)l * 2 * IN3H * HH,
            ulo + (size_t)l * 2 * IN3H * HH,
            bhh + (size_t)l * 2 * IN3H,
            out + (size_t)l * 2 * BB * HH);
    }
}

// round 13
// speedup vs baseline: 1.1266x; 1.1266x over previous
#include <cuda_runtime.h>
#include <cuda_bf16.h>
#include <math.h>
#include <stdint.h>
#include <stddef.h>

// Problem constants
#define TT 256
#define BB 64
#define HH 1024
#define IN3H 3072          // 3*H
#define INK 2048           // input width of every layer (IN = 2H)
#define GX_M (TT * BB)     // 16384
#define GXSZ ((size_t)GX_M * IN3H)

#define REC_BLOCKS 144     // 2 dirs * 24 N-tiles(128) * 3 K-splits
#define REC_THREADS 256

// ---------------------------------------------------------------------------
// Scratch (device globals -- no allocation allowed)
// ---------------------------------------------------------------------------
__device__ float g_gx[2 * GXSZ];                        // input gates (fp32)
__device__ float g_ghp[3][2][(size_t)BB * IN3H];        // hidden-gate partials
__device__ __nv_bfloat16 g_hhi[2 * BB * HH];            // hidden state hi/lo
__device__ __nv_bfloat16 g_hlo[2 * BB * HH];
__device__ __nv_bfloat16 g_ahi[(size_t)GX_M * INK];     // layer input hi/lo
__device__ __nv_bfloat16 g_alo[(size_t)GX_M * INK];
__device__ __nv_bfloat16 g_whi[(size_t)6 * IN3H * INK]; // w_ih hi/lo
__device__ __nv_bfloat16 g_wlo[(size_t)6 * IN3H * INK];
__device__ __nv_bfloat16 g_uhi[(size_t)6 * IN3H * HH];  // w_hh hi/lo
__device__ __nv_bfloat16 g_ulo[(size_t)6 * IN3H * HH];

__device__ unsigned g_bar_count = 0;
__device__ unsigned g_bar_phase = 0;

// ---------------------------------------------------------------------------
// Baseline-PTX helpers (valid on compute_103)
// ---------------------------------------------------------------------------
__device__ __forceinline__ uint32_t smem_u32(const void* p) {
    uint32_t a;
    asm("{ .reg .u64 t; cvta.to.shared.u64 t, %1; cvt.u32.u64 %0, t; }"
        : "=r"(a) : "l"(p));
    return a;
}

__device__ __forceinline__ void cp_async16(uint32_t dst, const void* src) {
    asm volatile("cp.async.cg.shared.global [%0], [%1], 16;"
                 :: "r"(dst), "l"(src) : "memory");
}
#define CP_COMMIT() asm volatile("cp.async.commit_group;" ::: "memory")
#define CP_WAIT0()  asm volatile("cp.async.wait_group 0;" ::: "memory")
#define CP_WAIT1()  asm volatile("cp.async.wait_group 1;" ::: "memory")

__device__ __forceinline__ void ldsm4(uint32_t* r, uint32_t addr) {
    asm volatile("ldmatrix.sync.aligned.m8n8.x4.shared.b16 {%0,%1,%2,%3}, [%4];"
                 : "=r"(r[0]), "=r"(r[1]), "=r"(r[2]), "=r"(r[3]) : "r"(addr));
}

__device__ __forceinline__ void mma_bf16(float* c, const uint32_t* a,
                                         uint32_t b0, uint32_t b1) {
    asm("mma.sync.aligned.m16n8k16.row.col.f32.bf16.bf16.f32 "
        "{%0,%1,%2,%3}, {%4,%5,%6,%7}, {%8,%9}, {%0,%1,%2,%3};"
        : "+f"(c[0]), "+f"(c[1]), "+f"(c[2]), "+f"(c[3])
        : "r"(a[0]), "r"(a[1]), "r"(a[2]), "r"(a[3]), "r"(b0), "r"(b1));
}

__device__ __forceinline__ void prefetch_l2(const void* p) {
    asm volatile("prefetch.global.L2 [%0];" :: "l"(p));
}

// ---------------------------------------------------------------------------
// Split fp32 -> (bf16 hi, bf16 lo)
// ---------------------------------------------------------------------------
__device__ __forceinline__ uint32_t pack2bf(float a, float b) {
    __nv_bfloat162 t = __floats2bfloat162_rn(a, b);
    return *(uint32_t*)&t;
}

__global__ __launch_bounds__(256) void split_bf16_kernel(
    const float* __restrict__ src, __nv_bfloat16* __restrict__ hi,
    __nv_bfloat16* __restrict__ lo, size_t n4) {
    size_t i = (size_t)blockIdx.x * 256 + threadIdx.x;
    if (i >= n4) return;
    float4 v = ((const float4*)src)[i];
    float h0 = __bfloat162float(__float2bfloat16(v.x));
    float h1 = __bfloat162float(__float2bfloat16(v.y));
    float h2 = __bfloat162float(__float2bfloat16(v.z));
    float h3 = __bfloat162float(__float2bfloat16(v.w));
    uint2 hv, lv;
    hv.x = pack2bf(v.x, v.y);           hv.y = pack2bf(v.z, v.w);
    lv.x = pack2bf(v.x - h0, v.y - h1); lv.y = pack2bf(v.z - h2, v.w - h3);
    ((uint2*)hi)[i] = hv;
    ((uint2*)lo)[i] = lv;
}

// ---------------------------------------------------------------------------
// gx GEMM R13: 128x128 tile, k-chunk 32, XOR-swizzled 64B rows (32KB/stage),
// 3-stage cp.async pipeline, 2 CTAs/SM, one __syncthreads per chunk.
// stage layout: Ahi@0, Alo@8192, Bhi@16384, Blo@24576 (128 rows x 64B each)
// ---------------------------------------------------------------------------
#define GX_STAGE 32768
#define GX_SMEM  (3 * GX_STAGE)
#define GX_NCHUNK 64

__device__ __forceinline__ void gx_load(uint32_t sm, int bm, int bn, int k0,
                                        int tid, const __nv_bfloat16* Bhi,
                                        const __nv_bfloat16* Blo) {
#pragma unroll
    for (int it = 0; it < 8; it++) {
        int idx = it * 256 + tid;        // 0..2047
        int mat = idx >> 9;              // constant per it
        int r   = (idx >> 2) & 127;
        int seg = idx & 3;
        int co  = k0 + seg * 8;
        uint32_t dst = sm + mat * 8192 + r * 64
                       + (uint32_t)((seg ^ ((r >> 1) & 3)) * 16);
        const __nv_bfloat16* src;
        if (mat == 0)      src = g_ahi + (size_t)(bm + r) * INK + co;
        else if (mat == 1) src = g_alo + (size_t)(bm + r) * INK + co;
        else if (mat == 2) src = Bhi   + (size_t)(bn + r) * INK + co;
        else               src = Blo   + (size_t)(bn + r) * INK + co;
        cp_async16(dst, src);
    }
}

__global__ __launch_bounds__(256, 2) void gx_mma_kernel(
    const __nv_bfloat16* __restrict__ Whi,
    const __nv_bfloat16* __restrict__ Wlo,
    const float* __restrict__ bias)
{
    extern __shared__ char smem[];
    const uint32_t sb = smem_u32(smem);
    const int tid = threadIdx.x, wid = tid >> 5, lid = tid & 31;
    const int bn = blockIdx.x * 128;
    const int bm = blockIdx.y * 128;
    const int d  = blockIdx.z;

    const __nv_bfloat16* Bhi = Whi + (size_t)d * IN3H * INK;
    const __nv_bfloat16* Blo = Wlo + (size_t)d * IN3H * INK;
    const float* bptr = bias + d * IN3H;
    float* C = g_gx + (size_t)d * GXSZ;

    // XOR-swizzle key: invariant to +8/+16/+32 row offsets
    const uint32_t key = (uint32_t)(((lid & 7) >> 1) & 3);
    // A fragment rows: (wid&3)*32 + (lid&7) + ((lid>>3)&1)*8
    const uint32_t abase = (uint32_t)(((wid & 3) * 32 + (lid & 7)
                                       + ((lid >> 3) & 1) * 8) * 64);
    const uint32_t ach = (uint32_t)((lid >> 4) & 1);   // A col-half
    // B fragment rows: (wid>>2)*64 + (lid&7) + ((lid>>4)&1)*8
    const uint32_t bbase = (uint32_t)(((wid >> 2) * 64 + (lid & 7)
                                       + ((lid >> 4) & 1) * 8) * 64);
    const uint32_t bch = (uint32_t)((lid >> 3) & 1);   // B col-half

    float acc[2][8][4];
#pragma unroll
    for (int i = 0; i < 2; i++)
#pragma unroll
        for (int j = 0; j < 8; j++)
#pragma unroll
            for (int q = 0; q < 4; q++) acc[i][j][q] = 0.f;

    gx_load(sb,            bm, bn,  0, tid, Bhi, Blo); CP_COMMIT();
    gx_load(sb + GX_STAGE, bm, bn, 32, tid, Bhi, Blo); CP_COMMIT();

    for (int c = 0; c < GX_NCHUNK; c++) {
        if (c + 1 < GX_NCHUNK) { CP_WAIT1(); } else { CP_WAIT0(); }
        __syncthreads();
        if (c + 2 < GX_NCHUNK) {
            gx_load(sb + ((c + 2) % 3) * GX_STAGE, bm, bn, (c + 2) * 32,
                    tid, Bhi, Blo);
            CP_COMMIT();
        }
        const uint32_t st = sb + (c % 3) * GX_STAGE;

#pragma unroll
        for (int kk = 0; kk < 2; kk++) {
            const uint32_t ak = ((kk * 2 + ach) ^ key) * 16;   // A seg offset
            const uint32_t bk = ((kk * 2 + bch) ^ key) * 16;   // B seg offset
            uint32_t ah[2][4], al[2][4];
            ldsm4(ah[0], st + abase + ak);
            ldsm4(ah[1], st + abase + 1024 + ak);          // +16 rows
            ldsm4(al[0], st + 8192 + abase + ak);
            ldsm4(al[1], st + 8192 + abase + 1024 + ak);
#pragma unroll
            for (int g = 0; g < 4; g++) {
                uint32_t bh[4], bl[4];
                ldsm4(bh, st + 16384 + bbase + g * 1024 + bk);
                ldsm4(bl, st + 24576 + bbase + g * 1024 + bk);
                mma_bf16(acc[0][2 * g],     ah[0], bh[0], bh[1]);
                mma_bf16(acc[0][2 * g + 1], ah[0], bh[2], bh[3]);
                mma_bf16(acc[1][2 * g],     ah[1], bh[0], bh[1]);
                mma_bf16(acc[1][2 * g + 1], ah[1], bh[2], bh[3]);
                mma_bf16(acc[0][2 * g],     ah[0], bl[0], bl[1]);
                mma_bf16(acc[0][2 * g + 1], ah[0], bl[2], bl[3]);
                mma_bf16(acc[1][2 * g],     ah[1], bl[0], bl[1]);
                mma_bf16(acc[1][2 * g + 1], ah[1], bl[2], bl[3]);
                mma_bf16(acc[0][2 * g],     al[0], bh[0], bh[1]);
                mma_bf16(acc[0][2 * g + 1], al[0], bh[2], bh[3]);
                mma_bf16(acc[1][2 * g],     al[1], bh[0], bh[1]);
                mma_bf16(acc[1][2 * g + 1], al[1], bh[2], bh[3]);
            }
        }
    }

    const int lr = lid >> 2;
    const int lc = (lid & 3) * 2;
#pragma unroll
    for (int mt = 0; mt < 2; mt++) {
        const int row = bm + (wid & 3) * 32 + mt * 16 + lr;
#pragma unroll
        for (int nt = 0; nt < 8; nt++) {
            const int col = bn + (wid >> 2) * 64 + nt * 8 + lc;
            float b0 = bptr[col], b1 = bptr[col + 1];
            float* c = acc[mt][nt];
            C[(size_t)row * IN3H + col]           = c[0] + b0;
            C[(size_t)row * IN3H + col + 1]       = c[1] + b1;
            C[(size_t)(row + 8) * IN3H + col]     = c[2] + b0;
            C[(size_t)(row + 8) * IN3H + col + 1] = c[3] + b1;
        }
    }
}

// ---------------------------------------------------------------------------
// Grid-wide barrier (spin, monotonic phase) -- proven R6
// ---------------------------------------------------------------------------
__device__ __forceinline__ void grid_sync(unsigned& local_phase) {
    __threadfence();
    __syncthreads();
    if (threadIdx.x == 0) {
        unsigned ph = local_phase;
        if (atomicAdd(&g_bar_count, 1u) == REC_BLOCKS - 1) {
            g_bar_count = 0;
            __threadfence();
            atomicAdd(&g_bar_phase, 1u);
        } else {
            while (*(volatile unsigned*)&g_bar_phase == ph) { }
        }
        __threadfence();
    }
    __syncthreads();
    local_phase++;
}

// ---------------------------------------------------------------------------
// Persistent recurrent kernel -- VERBATIM R12 (h state in registers; R11 gx
// prefetch; R6 GEMM/barrier structure).
// ---------------------------------------------------------------------------
#define RC_SB_BHI 20480
#define RC_SB_BLO 110592
#define RC_SMEM   200704

__global__ __launch_bounds__(REC_THREADS)
void gru_recurrent_kernel(const float* __restrict__ h0_layer,    // [2,B,H]
                          const __nv_bfloat16* __restrict__ Uhi, // [2,3H,H]
                          const __nv_bfloat16* __restrict__ Ulo,
                          const float* __restrict__ bhh_layer,   // [2,3H]
                          float* __restrict__ hn_out)            // [2,B,H]
{
    extern __shared__ char smem[];
    const uint32_t sb = smem_u32(smem);
    const int bid = blockIdx.x, tid = threadIdx.x;
    const int wid = tid >> 5, lid = tid & 31;
    const int d   = bid / 72;
    const int rem = bid % 72;
    const int nt  = rem / 3;            // 0..23 -> 128 gh columns each
    const int ks  = rem % 3;            // K split
    const int bn0  = nt * 128;
    const int kbeg = ks * 352;          // {0, 352, 704}
    const int nc   = (ks == 2) ? 10 : 11;   // chunks of 32 k

    const __nv_bfloat16* Whi = Uhi + (size_t)d * IN3H * HH;
    const __nv_bfloat16* Wlo = Ulo + (size_t)d * IN3H * HH;
    float* Pout = g_ghp[ks][d];

    unsigned phase = *(volatile unsigned*)&g_bar_phase;
    __syncthreads();

    // ---- One-time weight preload into resident smem (swizzled 64B rows) ----
    for (int idx = tid; idx < nc * 512; idx += REC_THREADS) {
        int chunk = idx >> 9;
        int r     = (idx >> 2) & 127;
        int seg   = idx & 3;
        int col   = kbeg + chunk * 32 + seg * 8;
        uint32_t dst = (uint32_t)(chunk * 8192 + r * 64
                                  + ((seg ^ ((r >> 1) & 3)) * 16));
        cp_async16(sb + RC_SB_BHI + dst, Whi + (size_t)(bn0 + r) * HH + col);
        cp_async16(sb + RC_SB_BLO + dst, Wlo + (size_t)(bn0 + r) * HH + col);
    }
    CP_COMMIT();
    CP_WAIT0();

    // Prologue: split h0 into bf16 hi/lo state buffers
    for (int i = bid * REC_THREADS + tid; i < 2 * BB * HH;
         i += REC_BLOCKS * REC_THREADS) {
        float v = h0_layer[i];
        __nv_bfloat16 hi = __float2bfloat16(v);
        g_hhi[i] = hi;
        g_hlo[i] = __float2bfloat16(v - __bfloat162float(hi));
    }

    // Per-thread gate-state registers (mapping p -> (d2,b,jp) step-invariant)
    float2 hreg[2];
    int pidx[2], pcnt = 0;
    {
        int p = bid * REC_THREADS + tid;
#pragma unroll
        for (int q = 0; q < 2; q++) {
            if (p < 65536) {
                pidx[pcnt] = p;
                const int d2 = p >> 15;
                const int rm = p & 32767;
                const int b  = rm >> 9;
                const int jp = (rm & 511) << 1;
                const int i  = d2 * BB * HH + b * HH + jp;
                hreg[pcnt] = *(const float2*)(h0_layer + i);
                pcnt++;
            }
            p += REC_BLOCKS * REC_THREADS;
        }
    }
    grid_sync(phase);

    const uint32_t aoff = (uint32_t)(((wid & 1) * 32 + (lid & 7) + ((lid >> 3) & 1) * 8) * 80
                                     + ((lid >> 4) & 1) * 16);
    const int brow0 = (wid >> 1) * 32 + (lid & 7) + ((lid >> 4) & 1) * 8;
    const int bkey  = (brow0 >> 1) & 3;
    const int lb3   = (lid >> 3) & 1;
    const uint32_t bseg0 = (uint32_t)(((0 + lb3) ^ bkey) * 16);
    const uint32_t bseg1 = (uint32_t)(((2 + lb3) ^ bkey) * 16);
    const uint32_t bbase = (uint32_t)(brow0 * 64);

    const __nv_bfloat16* hhi = g_hhi + (size_t)d * BB * HH;
    const __nv_bfloat16* hlo = g_hlo + (size_t)d * BB * HH;

    const int a_r  = tid >> 2;
    const int a_sg = tid & 3;

    for (int s = 0; s < TT; s++) {
        float acc[2][4][4];
#pragma unroll
        for (int i = 0; i < 2; i++)
#pragma unroll
            for (int j = 0; j < 4; j++)
#pragma unroll
                for (int q = 0; q < 4; q++) acc[i][j][q] = 0.f;

        {   // prologue A load, chunk 0
            uint32_t dst = sb + a_r * 80 + a_sg * 16;
            const int co = kbeg + a_sg * 8;
            cp_async16(dst,        hhi + (size_t)a_r * HH + co);
            cp_async16(dst + 5120, hlo + (size_t)a_r * HH + co);
            CP_COMMIT();
        }

        // Prefetch this step's gx rows into L2 (R11 win)
        {
            const int ln = bid * REC_THREADS + tid;
            if (ln < 6144) {
                prefetch_l2(g_gx + (size_t)s * BB * IN3H + (size_t)ln * 32);
            } else if (ln < 12288) {
                prefetch_l2(g_gx + GXSZ + (size_t)(TT - 1 - s) * BB * IN3H
                            + (size_t)(ln - 6144) * 32);
            }
        }

        for (int c = 0; c < nc; c++) {
            if (c + 1 < nc) {
                uint32_t dst = sb + ((c + 1) & 1) * 10240 + a_r * 80 + a_sg * 16;
                const int co = kbeg + (c + 1) * 32 + a_sg * 8;
                cp_async16(dst,        hhi + (size_t)a_r * HH + co);
                cp_async16(dst + 5120, hlo + (size_t)a_r * HH + co);
                CP_COMMIT();
                CP_WAIT1();
            } else {
                CP_WAIT0();
            }
            __syncthreads();
            const uint32_t stA  = sb + (c & 1) * 10240;
            const uint32_t stBh = sb + RC_SB_BHI + c * 8192 + bbase;
            const uint32_t stBl = sb + RC_SB_BLO + c * 8192 + bbase;

#pragma unroll
            for (int kk = 0; kk < 2; kk++) {
                const uint32_t ko  = kk * 32;
                const uint32_t bso = kk ? bseg1 : bseg0;
                uint32_t ah[2][4], al[2][4], bh[2][4], bl[2][4];
                ldsm4(ah[0], stA + aoff + ko);
                ldsm4(ah[1], stA + aoff + 1280 + ko);
                ldsm4(al[0], stA + 5120 + aoff + ko);
                ldsm4(al[1], stA + 5120 + aoff + 1280 + ko);
                ldsm4(bh[0], stBh + bso);
                ldsm4(bh[1], stBh + 1024 + bso);
                ldsm4(bl[0], stBl + bso);
                ldsm4(bl[1], stBl + 1024 + bso);
#pragma unroll
                for (int mt = 0; mt < 2; mt++)
#pragma unroll
                    for (int g = 0; g < 2; g++) {
                        mma_bf16(acc[mt][2 * g],     ah[mt], bh[g][0], bh[g][1]);
                        mma_bf16(acc[mt][2 * g + 1], ah[mt], bh[g][2], bh[g][3]);
                    }
#pragma unroll
                for (int mt = 0; mt < 2; mt++)
#pragma unroll
                    for (int g = 0; g < 2; g++) {
                        mma_bf16(acc[mt][2 * g],     ah[mt], bl[g][0], bl[g][1]);
                        mma_bf16(acc[mt][2 * g + 1], ah[mt], bl[g][2], bl[g][3]);
                    }
#pragma unroll
                for (int mt = 0; mt < 2; mt++)
#pragma unroll
                    for (int g = 0; g < 2; g++) {
                        mma_bf16(acc[mt][2 * g],     al[mt], bh[g][0], bh[g][1]);
                        mma_bf16(acc[mt][2 * g + 1], al[mt], bh[g][2], bh[g][3]);
                    }
            }
            __syncthreads();
        }

        // Epilogue: write 64x128 partial tile
        {
            const int lr = lid >> 2;
            const int lc = (lid & 3) * 2;
#pragma unroll
            for (int mt = 0; mt < 2; mt++) {
                const int row = (wid & 1) * 32 + mt * 16 + lr;
#pragma unroll
                for (int j = 0; j < 4; j++) {
                    const int col = bn0 + (wid >> 1) * 32 + j * 8 + lc;
                    float* c = acc[mt][j];
                    Pout[(size_t)row * IN3H + col]           = c[0];
                    Pout[(size_t)row * IN3H + col + 1]       = c[1];
                    Pout[(size_t)(row + 8) * IN3H + col]     = c[2];
                    Pout[(size_t)(row + 8) * IN3H + col + 1] = c[3];
                }
            }
        }

        grid_sync(phase);

        // Gate phase -- float2 vectorized; h state in registers
#pragma unroll
        for (int q2 = 0; q2 < 2; q2++) {
            if (q2 >= pcnt) break;
            const int p  = pidx[q2];
            const int d2 = p >> 15;
            const int rm = p & 32767;
            const int b  = rm >> 9;
            const int jp = (rm & 511) << 1;
            const int i  = d2 * BB * HH + b * HH + jp;
            const int t  = d2 ? (TT - 1 - s) : s;

            const float* gxp = g_gx + (size_t)d2 * GXSZ + ((size_t)t * BB + b) * IN3H;
            const float* P0 = g_ghp[0][d2] + (size_t)b * IN3H;
            const float* P1 = g_ghp[1][d2] + (size_t)b * IN3H;
            const float* P2 = g_ghp[2][d2] + (size_t)b * IN3H;
            const float* bias2 = bhh_layer + d2 * IN3H;

            float2 gr  = *(const float2*)(gxp + jp);
            float2 gz  = *(const float2*)(gxp + HH + jp);
            float2 gn  = *(const float2*)(gxp + 2 * HH + jp);
            float2 p0r = *(const float2*)(P0 + jp);
            float2 p0z = *(const float2*)(P0 + HH + jp);
            float2 p0n = *(const float2*)(P0 + 2 * HH + jp);
            float2 p1r = *(const float2*)(P1 + jp);
            float2 p1z = *(const float2*)(P1 + HH + jp);
            float2 p1n = *(const float2*)(P1 + 2 * HH + jp);
            float2 p2r = *(const float2*)(P2 + jp);
            float2 p2z = *(const float2*)(P2 + HH + jp);
            float2 p2n = *(const float2*)(P2 + 2 * HH + jp);
            float2 br  = *(const float2*)(bias2 + jp);
            float2 bz  = *(const float2*)(bias2 + HH + jp);
            float2 bn2 = *(const float2*)(bias2 + 2 * HH + jp);

            float hnew[2];
#pragma unroll
            for (int q = 0; q < 2; q++) {
                float ghr = (q ? p0r.y + p1r.y + p2r.y + br.y
                               : p0r.x + p1r.x + p2r.x + br.x);
                float ghz = (q ? p0z.y + p1z.y + p2z.y + bz.y
                               : p0z.x + p1z.x + p2z.x + bz.x);
                float ghn = (q ? p0n.y + p1n.y + p2n.y + bn2.y
                               : p0n.x + p1n.x + p2n.x + bn2.x);
                float gxr = q ? gr.y : gr.x;
                float gxz = q ? gz.y : gz.x;
                float gxn = q ? gn.y : gn.x;
                float hol = q ? hreg[q2].y : hreg[q2].x;

                float r = 1.f / (1.f + expf(-(gxr + ghr)));
                float z = 1.f / (1.f + expf(-(gxz + ghz)));
                float n = tanhf(gxn + r * ghn);
                hnew[q] = n + z * (hol - n);
            }

            hreg[q2] = make_float2(hnew[0], hnew[1]);

            __nv_bfloat162 h2 = __floats2bfloat162_rn(hnew[0], hnew[1]);
            float r0 = hnew[0] - __bfloat162float(__low2bfloat16(h2));
            float r1 = hnew[1] - __bfloat162float(__high2bfloat16(h2));
            __nv_bfloat162 l2v = __floats2bfloat162_rn(r0, r1);

            *(__nv_bfloat162*)(g_hhi + i) = h2;
            *(__nv_bfloat162*)(g_hlo + i) = l2v;

            size_t oidx = ((size_t)t * BB + b) * INK + (size_t)d2 * HH + jp;
            *(__nv_bfloat162*)(g_ahi + oidx) = h2;
            *(__nv_bfloat162*)(g_alo + oidx) = l2v;

            if (s == TT - 1) *(float2*)(hn_out + i) = hreg[q2];
        }

        grid_sync(phase);
    }
}

// ---------------------------------------------------------------------------
// Launch
// ---------------------------------------------------------------------------
extern "C" void kernel_launch(void* const* d_in, const int* in_sizes, int n_in,
                              void* d_out, int out_size) {
    const float* x   = (const float*)d_in[0];  // [T, B, 2048]
    const float* h0  = (const float*)d_in[1];  // [6, B, H]
    const float* wih = (const float*)d_in[2];  // [3, 2, 3072, 2048]
    const float* whh = (const float*)d_in[3];  // [3, 2, 3072, 1024]
    const float* bih = (const float*)d_in[4];  // [3, 2, 3072]
    const float* bhh = (const float*)d_in[5];  // [3, 2, 3072]
    float* out = (float*)d_out;                // [6, B, H]

    __nv_bfloat16 *ahi, *alo, *whi, *wlo, *uhi, *ulo;
    cudaGetSymbolAddress((void**)&ahi, g_ahi);
    cudaGetSymbolAddress((void**)&alo, g_alo);
    cudaGetSymbolAddress((void**)&whi, g_whi);
    cudaGetSymbolAddress((void**)&wlo, g_wlo);
    cudaGetSymbolAddress((void**)&uhi, g_uhi);
    cudaGetSymbolAddress((void**)&ulo, g_ulo);

    cudaFuncSetAttribute(gx_mma_kernel,
                         cudaFuncAttributeMaxDynamicSharedMemorySize, GX_SMEM);
    cudaFuncSetAttribute(gru_recurrent_kernel,
                         cudaFuncAttributeMaxDynamicSharedMemorySize, RC_SMEM);

    {   // split w_ih
        size_t n4 = (size_t)6 * IN3H * INK / 4;
        split_bf16_kernel<<<(unsigned)((n4 + 255) / 256), 256>>>(wih, whi, wlo, n4);
    }
    {   // split w_hh
        size_t n4 = (size_t)6 * IN3H * HH / 4;
        split_bf16_kernel<<<(unsigned)((n4 + 255) / 256), 256>>>(whh, uhi, ulo, n4);
    }
    {   // split x (layer-0 input)
        size_t n4 = (size_t)GX_M * INK / 4;
        split_bf16_kernel<<<(unsigned)((n4 + 255) / 256), 256>>>(x, ahi, alo, n4);
    }

    for (int l = 0; l < 3; l++) {
        gx_mma_kernel<<<dim3(IN3H / 128, GX_M / 128, 2), 256, GX_SMEM>>>(
            whi + (size_t)l * 2 * IN3H * INK,
            wlo + (size_t)l * 2 * IN3H * INK,
            bih + (size_t)l * 2 * IN3H);

        gru_recurrent_kernel<<<REC_BLOCKS, REC_THREADS, RC_SMEM>>>(
            h0  + (size_t)l * 2 * BB * HH,
            uhi + (size_t)l * 2 * IN3H * HH,
            ulo + (size_t)l * 2 * IN3H * HH,
            bhh + (size_t)l * 2 * IN3H,
            out + (size_t)l * 2 * BB * HH);
    }
}

// round 14
// speedup vs baseline: 1.1361x; 1.0084x over previous
#include <cuda_runtime.h>
#include <cuda_bf16.h>
#include <math.h>
#include <stdint.h>
#include <stddef.h>

// Problem constants
#define TT 256
#define BB 64
#define HH 1024
#define IN3H 3072          // 3*H
#define INK 2048           // input width of every layer (IN = 2H)
#define GX_M (TT * BB)     // 16384
#define GXSZ ((size_t)GX_M * IN3H)

#define REC_BLOCKS 144     // 2 dirs * 24 N-tiles(128) * 3 K-splits
#define REC_THREADS 256

// ---------------------------------------------------------------------------
// Scratch (device globals -- no allocation allowed)
// ---------------------------------------------------------------------------
__device__ float g_gx[2 * GXSZ];                        // input gates (fp32)
__device__ float g_ghp[3][2][(size_t)BB * IN3H];        // hidden-gate partials
__device__ __nv_bfloat16 g_hhi[2 * BB * HH];            // hidden state hi/lo
__device__ __nv_bfloat16 g_hlo[2 * BB * HH];
__device__ __nv_bfloat16 g_ahi[(size_t)GX_M * INK];     // layer input hi/lo
__device__ __nv_bfloat16 g_alo[(size_t)GX_M * INK];
__device__ __nv_bfloat16 g_whi[(size_t)6 * IN3H * INK]; // w_ih hi/lo
__device__ __nv_bfloat16 g_wlo[(size_t)6 * IN3H * INK];
__device__ __nv_bfloat16 g_uhi[(size_t)6 * IN3H * HH];  // w_hh hi/lo
__device__ __nv_bfloat16 g_ulo[(size_t)6 * IN3H * HH];

__device__ unsigned g_bar_count = 0;
__device__ unsigned g_bar_phase = 0;

// ---------------------------------------------------------------------------
// Baseline-PTX helpers (valid on compute_103)
// ---------------------------------------------------------------------------
__device__ __forceinline__ uint32_t smem_u32(const void* p) {
    uint32_t a;
    asm("{ .reg .u64 t; cvta.to.shared.u64 t, %1; cvt.u32.u64 %0, t; }"
        : "=r"(a) : "l"(p));
    return a;
}

__device__ __forceinline__ void cp_async16(uint32_t dst, const void* src) {
    asm volatile("cp.async.cg.shared.global [%0], [%1], 16;"
                 :: "r"(dst), "l"(src) : "memory");
}
#define CP_COMMIT() asm volatile("cp.async.commit_group;" ::: "memory")
#define CP_WAIT0()  asm volatile("cp.async.wait_group 0;" ::: "memory")
#define CP_WAIT1()  asm volatile("cp.async.wait_group 1;" ::: "memory")

__device__ __forceinline__ void ldsm4(uint32_t* r, uint32_t addr) {
    asm volatile("ldmatrix.sync.aligned.m8n8.x4.shared.b16 {%0,%1,%2,%3}, [%4];"
                 : "=r"(r[0]), "=r"(r[1]), "=r"(r[2]), "=r"(r[3]) : "r"(addr));
}

__device__ __forceinline__ void mma_bf16(float* c, const uint32_t* a,
                                         uint32_t b0, uint32_t b1) {
    asm("mma.sync.aligned.m16n8k16.row.col.f32.bf16.bf16.f32 "
        "{%0,%1,%2,%3}, {%4,%5,%6,%7}, {%8,%9}, {%0,%1,%2,%3};"
        : "+f"(c[0]), "+f"(c[1]), "+f"(c[2]), "+f"(c[3])
        : "r"(a[0]), "r"(a[1]), "r"(a[2]), "r"(a[3]), "r"(b0), "r"(b1));
}

__device__ __forceinline__ void prefetch_l2(const void* p) {
    asm volatile("prefetch.global.L2 [%0];" :: "l"(p));
}

// ---------------------------------------------------------------------------
// Split fp32 -> (bf16 hi, bf16 lo)
// ---------------------------------------------------------------------------
__device__ __forceinline__ uint32_t pack2bf(float a, float b) {
    __nv_bfloat162 t = __floats2bfloat162_rn(a, b);
    return *(uint32_t*)&t;
}

__global__ __launch_bounds__(256) void split_bf16_kernel(
    const float* __restrict__ src, __nv_bfloat16* __restrict__ hi,
    __nv_bfloat16* __restrict__ lo, size_t n4) {
    size_t i = (size_t)blockIdx.x * 256 + threadIdx.x;
    if (i >= n4) return;
    float4 v = ((const float4*)src)[i];
    float h0 = __bfloat162float(__float2bfloat16(v.x));
    float h1 = __bfloat162float(__float2bfloat16(v.y));
    float h2 = __bfloat162float(__float2bfloat16(v.z));
    float h3 = __bfloat162float(__float2bfloat16(v.w));
    uint2 hv, lv;
    hv.x = pack2bf(v.x, v.y);           hv.y = pack2bf(v.z, v.w);
    lv.x = pack2bf(v.x - h0, v.y - h1); lv.y = pack2bf(v.z - h2, v.w - h3);
    ((uint2*)hi)[i] = hv;
    ((uint2*)lo)[i] = lv;
}

// ---------------------------------------------------------------------------
// gx GEMM -- VERBATIM R13 (75.1% tensor): 128x128 tile, k-chunk 32,
// XOR-swizzled 64B rows, 3-stage cp.async, 2 CTAs/SM, one sync per chunk.
// ---------------------------------------------------------------------------
#define GX_STAGE 32768
#define GX_SMEM  (3 * GX_STAGE)
#define GX_NCHUNK 64

__device__ __forceinline__ void gx_load(uint32_t sm, int bm, int bn, int k0,
                                        int tid, const __nv_bfloat16* Bhi,
                                        const __nv_bfloat16* Blo) {
#pragma unroll
    for (int it = 0; it < 8; it++) {
        int idx = it * 256 + tid;        // 0..2047
        int mat = idx >> 9;              // constant per it
        int r   = (idx >> 2) & 127;
        int seg = idx & 3;
        int co  = k0 + seg * 8;
        uint32_t dst = sm + mat * 8192 + r * 64
                       + (uint32_t)((seg ^ ((r >> 1) & 3)) * 16);
        const __nv_bfloat16* src;
        if (mat == 0)      src = g_ahi + (size_t)(bm + r) * INK + co;
        else if (mat == 1) src = g_alo + (size_t)(bm + r) * INK + co;
        else if (mat == 2) src = Bhi   + (size_t)(bn + r) * INK + co;
        else               src = Blo   + (size_t)(bn + r) * INK + co;
        cp_async16(dst, src);
    }
}

__global__ __launch_bounds__(256, 2) void gx_mma_kernel(
    const __nv_bfloat16* __restrict__ Whi,
    const __nv_bfloat16* __restrict__ Wlo,
    const float* __restrict__ bias)
{
    extern __shared__ char smem[];
    const uint32_t sb = smem_u32(smem);
    const int tid = threadIdx.x, wid = tid >> 5, lid = tid & 31;
    const int bn = blockIdx.x * 128;
    const int bm = blockIdx.y * 128;
    const int d  = blockIdx.z;

    const __nv_bfloat16* Bhi = Whi + (size_t)d * IN3H * INK;
    const __nv_bfloat16* Blo = Wlo + (size_t)d * IN3H * INK;
    const float* bptr = bias + d * IN3H;
    float* C = g_gx + (size_t)d * GXSZ;

    const uint32_t key = (uint32_t)(((lid & 7) >> 1) & 3);
    const uint32_t abase = (uint32_t)(((wid & 3) * 32 + (lid & 7)
                                       + ((lid >> 3) & 1) * 8) * 64);
    const uint32_t ach = (uint32_t)((lid >> 4) & 1);
    const uint32_t bbase = (uint32_t)(((wid >> 2) * 64 + (lid & 7)
                                       + ((lid >> 4) & 1) * 8) * 64);
    const uint32_t bch = (uint32_t)((lid >> 3) & 1);

    float acc[2][8][4];
#pragma unroll
    for (int i = 0; i < 2; i++)
#pragma unroll
        for (int j = 0; j < 8; j++)
#pragma unroll
            for (int q = 0; q < 4; q++) acc[i][j][q] = 0.f;

    gx_load(sb,            bm, bn,  0, tid, Bhi, Blo); CP_COMMIT();
    gx_load(sb + GX_STAGE, bm, bn, 32, tid, Bhi, Blo); CP_COMMIT();

    for (int c = 0; c < GX_NCHUNK; c++) {
        if (c + 1 < GX_NCHUNK) { CP_WAIT1(); } else { CP_WAIT0(); }
        __syncthreads();
        if (c + 2 < GX_NCHUNK) {
            gx_load(sb + ((c + 2) % 3) * GX_STAGE, bm, bn, (c + 2) * 32,
                    tid, Bhi, Blo);
            CP_COMMIT();
        }
        const uint32_t st = sb + (c % 3) * GX_STAGE;

#pragma unroll
        for (int kk = 0; kk < 2; kk++) {
            const uint32_t ak = ((kk * 2 + ach) ^ key) * 16;
            const uint32_t bk = ((kk * 2 + bch) ^ key) * 16;
            uint32_t ah[2][4], al[2][4];
            ldsm4(ah[0], st + abase + ak);
            ldsm4(ah[1], st + abase + 1024 + ak);
            ldsm4(al[0], st + 8192 + abase + ak);
            ldsm4(al[1], st + 8192 + abase + 1024 + ak);
#pragma unroll
            for (int g = 0; g < 4; g++) {
                uint32_t bh[4], bl[4];
                ldsm4(bh, st + 16384 + bbase + g * 1024 + bk);
                ldsm4(bl, st + 24576 + bbase + g * 1024 + bk);
                mma_bf16(acc[0][2 * g],     ah[0], bh[0], bh[1]);
                mma_bf16(acc[0][2 * g + 1], ah[0], bh[2], bh[3]);
                mma_bf16(acc[1][2 * g],     ah[1], bh[0], bh[1]);
                mma_bf16(acc[1][2 * g + 1], ah[1], bh[2], bh[3]);
                mma_bf16(acc[0][2 * g],     ah[0], bl[0], bl[1]);
                mma_bf16(acc[0][2 * g + 1], ah[0], bl[2], bl[3]);
                mma_bf16(acc[1][2 * g],     ah[1], bl[0], bl[1]);
                mma_bf16(acc[1][2 * g + 1], ah[1], bl[2], bl[3]);
                mma_bf16(acc[0][2 * g],     al[0], bh[0], bh[1]);
                mma_bf16(acc[0][2 * g + 1], al[0], bh[2], bh[3]);
                mma_bf16(acc[1][2 * g],     al[1], bh[0], bh[1]);
                mma_bf16(acc[1][2 * g + 1], al[1], bh[2], bh[3]);
            }
        }
    }

    const int lr = lid >> 2;
    const int lc = (lid & 3) * 2;
#pragma unroll
    for (int mt = 0; mt < 2; mt++) {
        const int row = bm + (wid & 3) * 32 + mt * 16 + lr;
#pragma unroll
        for (int nt = 0; nt < 8; nt++) {
            const int col = bn + (wid >> 2) * 64 + nt * 8 + lc;
            float b0 = bptr[col], b1 = bptr[col + 1];
            float* c = acc[mt][nt];
            C[(size_t)row * IN3H + col]           = c[0] + b0;
            C[(size_t)row * IN3H + col + 1]       = c[1] + b1;
            C[(size_t)(row + 8) * IN3H + col]     = c[2] + b0;
            C[(size_t)(row + 8) * IN3H + col + 1] = c[3] + b1;
        }
    }
}

// ---------------------------------------------------------------------------
// Grid-wide barrier (spin, monotonic phase) -- proven R6
// ---------------------------------------------------------------------------
__device__ __forceinline__ void grid_sync(unsigned& local_phase) {
    __threadfence();
    __syncthreads();
    if (threadIdx.x == 0) {
        unsigned ph = local_phase;
        if (atomicAdd(&g_bar_count, 1u) == REC_BLOCKS - 1) {
            g_bar_count = 0;
            __threadfence();
            atomicAdd(&g_bar_phase, 1u);
        } else {
            while (*(volatile unsigned*)&g_bar_phase == ph) { }
        }
        __threadfence();
    }
    __syncthreads();
    local_phase++;
}

// ---------------------------------------------------------------------------
// Persistent recurrent kernel R14: A-path rebuilt with the R13 recipe --
// XOR-swizzled 64B rows (8KB/stage), 3-stage cp.async, ONE sync per chunk.
// Gate phase / prefetch / barrier / h-registers identical to R12/R13.
// smem map (dynamic, 204800 B):
//   A stages: [3][ hi 4096 | lo 4096 ]              @ 0      (24576)
//   B hi:     [chunk][128 rows][64 B, swizzled]     @ 24576  (90112)
//   B lo:                                           @ 114688 (90112)
// ---------------------------------------------------------------------------
#define RC_SB_BHI 24576
#define RC_SB_BLO 114688
#define RC_SMEM   204800

__device__ __forceinline__ void rec_loadA(uint32_t stage,
                                          const __nv_bfloat16* hhi,
                                          const __nv_bfloat16* hlo,
                                          int k0, int tid) {
    int r   = tid >> 2;          // 0..63
    int seg = tid & 3;
    int co  = k0 + seg * 8;
    uint32_t off = (uint32_t)(r * 64 + ((seg ^ ((r >> 1) & 3)) * 16));
    cp_async16(stage + off,        hhi + (size_t)r * HH + co);
    cp_async16(stage + 4096 + off, hlo + (size_t)r * HH + co);
}

__global__ __launch_bounds__(REC_THREADS)
void gru_recurrent_kernel(const float* __restrict__ h0_layer,    // [2,B,H]
                          const __nv_bfloat16* __restrict__ Uhi, // [2,3H,H]
                          const __nv_bfloat16* __restrict__ Ulo,
                          const float* __restrict__ bhh_layer,   // [2,3H]
                          float* __restrict__ hn_out)            // [2,B,H]
{
    extern __shared__ char smem[];
    const uint32_t sb = smem_u32(smem);
    const int bid = blockIdx.x, tid = threadIdx.x;
    const int wid = tid >> 5, lid = tid & 31;
    const int d   = bid / 72;
    const int rem = bid % 72;
    const int nt  = rem / 3;            // 0..23 -> 128 gh columns each
    const int ks  = rem % 3;            // K split
    const int bn0  = nt * 128;
    const int kbeg = ks * 352;          // {0, 352, 704}
    const int nc   = (ks == 2) ? 10 : 11;   // chunks of 32 k

    const __nv_bfloat16* Whi = Uhi + (size_t)d * IN3H * HH;
    const __nv_bfloat16* Wlo = Ulo + (size_t)d * IN3H * HH;
    float* Pout = g_ghp[ks][d];

    unsigned phase = *(volatile unsigned*)&g_bar_phase;
    __syncthreads();

    // ---- One-time weight preload into resident smem (swizzled 64B rows) ----
    for (int idx = tid; idx < nc * 512; idx += REC_THREADS) {
        int chunk = idx >> 9;
        int r     = (idx >> 2) & 127;
        int seg   = idx & 3;
        int col   = kbeg + chunk * 32 + seg * 8;
        uint32_t dst = (uint32_t)(chunk * 8192 + r * 64
                                  + ((seg ^ ((r >> 1) & 3)) * 16));
        cp_async16(sb + RC_SB_BHI + dst, Whi + (size_t)(bn0 + r) * HH + col);
        cp_async16(sb + RC_SB_BLO + dst, Wlo + (size_t)(bn0 + r) * HH + col);
    }
    CP_COMMIT();
    CP_WAIT0();

    // Prologue: split h0 into bf16 hi/lo state buffers
    for (int i = bid * REC_THREADS + tid; i < 2 * BB * HH;
         i += REC_BLOCKS * REC_THREADS) {
        float v = h0_layer[i];
        __nv_bfloat16 hi = __float2bfloat16(v);
        g_hhi[i] = hi;
        g_hlo[i] = __float2bfloat16(v - __bfloat162float(hi));
    }

    // Per-thread gate-state registers (mapping p -> (d2,b,jp) step-invariant)
    float2 hreg[2];
    int pidx[2], pcnt = 0;
    {
        int p = bid * REC_THREADS + tid;
#pragma unroll
        for (int q = 0; q < 2; q++) {
            if (p < 65536) {
                pidx[pcnt] = p;
                const int d2 = p >> 15;
                const int rm = p & 32767;
                const int b  = rm >> 9;
                const int jp = (rm & 511) << 1;
                const int i  = d2 * BB * HH + b * HH + jp;
                hreg[pcnt] = *(const float2*)(h0_layer + i);
                pcnt++;
            }
            p += REC_BLOCKS * REC_THREADS;
        }
    }
    grid_sync(phase);

    // A ldmatrix (64B swizzled rows): warp m = (wid&1)*32
    const uint32_t key   = (uint32_t)(((lid & 7) >> 1) & 3);
    const uint32_t abase = (uint32_t)(((wid & 1) * 32 + (lid & 7)
                                       + ((lid >> 3) & 1) * 8) * 64);
    const uint32_t ach   = (uint32_t)((lid >> 4) & 1);
    // B ldmatrix (64B rows, XOR swizzle): warp n = (wid>>1)*32
    const int brow0 = (wid >> 1) * 32 + (lid & 7) + ((lid >> 4) & 1) * 8;
    const int bkey  = (brow0 >> 1) & 3;
    const int lb3   = (lid >> 3) & 1;
    const uint32_t bseg0 = (uint32_t)(((0 + lb3) ^ bkey) * 16);
    const uint32_t bseg1 = (uint32_t)(((2 + lb3) ^ bkey) * 16);
    const uint32_t bbase = (uint32_t)(brow0 * 64);

    const __nv_bfloat16* hhi = g_hhi + (size_t)d * BB * HH;
    const __nv_bfloat16* hlo = g_hlo + (size_t)d * BB * HH;

    for (int s = 0; s < TT; s++) {
        float acc[2][4][4];
#pragma unroll
        for (int i = 0; i < 2; i++)
#pragma unroll
            for (int j = 0; j < 4; j++)
#pragma unroll
                for (int q = 0; q < 4; q++) acc[i][j][q] = 0.f;

        // Prologue: chunks 0,1 into stages 0,1
        rec_loadA(sb,        hhi, hlo, kbeg,      tid); CP_COMMIT();
        rec_loadA(sb + 8192, hhi, hlo, kbeg + 32, tid); CP_COMMIT();

        // Prefetch this step's gx rows into L2 (R11 win)
        {
            const int ln = bid * REC_THREADS + tid;
            if (ln < 6144) {
                prefetch_l2(g_gx + (size_t)s * BB * IN3H + (size_t)ln * 32);
            } else if (ln < 12288) {
                prefetch_l2(g_gx + GXSZ + (size_t)(TT - 1 - s) * BB * IN3H
                            + (size_t)(ln - 6144) * 32);
            }
        }

        for (int c = 0; c < nc; c++) {
            if (c + 1 < nc) { CP_WAIT1(); } else { CP_WAIT0(); }
            __syncthreads();
            if (c + 2 < nc) {
                rec_loadA(sb + ((c + 2) % 3) * 8192, hhi, hlo,
                          kbeg + (c + 2) * 32, tid);
                CP_COMMIT();
            }
            const uint32_t stA  = sb + (c % 3) * 8192;
            const uint32_t stBh = sb + RC_SB_BHI + c * 8192 + bbase;
            const uint32_t stBl = sb + RC_SB_BLO + c * 8192 + bbase;

#pragma unroll
            for (int kk = 0; kk < 2; kk++) {
                const uint32_t ak  = ((kk * 2 + ach) ^ key) * 16;
                const uint32_t bso = kk ? bseg1 : bseg0;
                uint32_t ah[2][4], al[2][4], bh[2][4], bl[2][4];
                ldsm4(ah[0], stA + abase + ak);
                ldsm4(ah[1], stA + abase + 1024 + ak);       // +16 rows
                ldsm4(al[0], stA + 4096 + abase + ak);
                ldsm4(al[1], stA + 4096 + abase + 1024 + ak);
                ldsm4(bh[0], stBh + bso);
                ldsm4(bh[1], stBh + 1024 + bso);
                ldsm4(bl[0], stBl + bso);
                ldsm4(bl[1], stBl + 1024 + bso);
#pragma unroll
                for (int mt = 0; mt < 2; mt++)
#pragma unroll
                    for (int g = 0; g < 2; g++) {
                        mma_bf16(acc[mt][2 * g],     ah[mt], bh[g][0], bh[g][1]);
                        mma_bf16(acc[mt][2 * g + 1], ah[mt], bh[g][2], bh[g][3]);
                    }
#pragma unroll
                for (int mt = 0; mt < 2; mt++)
#pragma unroll
                    for (int g = 0; g < 2; g++) {
                        mma_bf16(acc[mt][2 * g],     ah[mt], bl[g][0], bl[g][1]);
                        mma_bf16(acc[mt][2 * g + 1], ah[mt], bl[g][2], bl[g][3]);
                    }
#pragma unroll
                for (int mt = 0; mt < 2; mt++)
#pragma unroll
                    for (int g = 0; g < 2; g++) {
                        mma_bf16(acc[mt][2 * g],     al[mt], bh[g][0], bh[g][1]);
                        mma_bf16(acc[mt][2 * g + 1], al[mt], bh[g][2], bh[g][3]);
                    }
            }
        }

        // Epilogue: write 64x128 partial tile
        {
            const int lr = lid >> 2;
            const int lc = (lid & 3) * 2;
#pragma unroll
            for (int mt = 0; mt < 2; mt++) {
                const int row = (wid & 1) * 32 + mt * 16 + lr;
#pragma unroll
                for (int j = 0; j < 4; j++) {
                    const int col = bn0 + (wid >> 1) * 32 + j * 8 + lc;
                    float* c = acc[mt][j];
                    Pout[(size_t)row * IN3H + col]           = c[0];
                    Pout[(size_t)row * IN3H + col + 1]       = c[1];
                    Pout[(size_t)(row + 8) * IN3H + col]     = c[2];
                    Pout[(size_t)(row + 8) * IN3H + col + 1] = c[3];
                }
            }
        }

        grid_sync(phase);

        // Gate phase -- float2 vectorized; h state in registers
#pragma unroll
        for (int q2 = 0; q2 < 2; q2++) {
            if (q2 >= pcnt) break;
            const int p  = pidx[q2];
            const int d2 = p >> 15;
            const int rm = p & 32767;
            const int b  = rm >> 9;
            const int jp = (rm & 511) << 1;
            const int i  = d2 * BB * HH + b * HH + jp;
            const int t  = d2 ? (TT - 1 - s) : s;

            const float* gxp = g_gx + (size_t)d2 * GXSZ + ((size_t)t * BB + b) * IN3H;
            const float* P0 = g_ghp[0][d2] + (size_t)b * IN3H;
            const float* P1 = g_ghp[1][d2] + (size_t)b * IN3H;
            const float* P2 = g_ghp[2][d2] + (size_t)b * IN3H;
            const float* bias2 = bhh_layer + d2 * IN3H;

            float2 gr  = *(const float2*)(gxp + jp);
            float2 gz  = *(const float2*)(gxp + HH + jp);
            float2 gn  = *(const float2*)(gxp + 2 * HH + jp);
            float2 p0r = *(const float2*)(P0 + jp);
            float2 p0z = *(const float2*)(P0 + HH + jp);
            float2 p0n = *(const float2*)(P0 + 2 * HH + jp);
            float2 p1r = *(const float2*)(P1 + jp);
            float2 p1z = *(const float2*)(P1 + HH + jp);
            float2 p1n = *(const float2*)(P1 + 2 * HH + jp);
            float2 p2r = *(const float2*)(P2 + jp);
            float2 p2z = *(const float2*)(P2 + HH + jp);
            float2 p2n = *(const float2*)(P2 + 2 * HH + jp);
            float2 br  = *(const float2*)(bias2 + jp);
            float2 bz  = *(const float2*)(bias2 + HH + jp);
            float2 bn2 = *(const float2*)(bias2 + 2 * HH + jp);

            float hnew[2];
#pragma unroll
            for (int q = 0; q < 2; q++) {
                float ghr = (q ? p0r.y + p1r.y + p2r.y + br.y
                               : p0r.x + p1r.x + p2r.x + br.x);
                float ghz = (q ? p0z.y + p1z.y + p2z.y + bz.y
                               : p0z.x + p1z.x + p2z.x + bz.x);
                float ghn = (q ? p0n.y + p1n.y + p2n.y + bn2.y
                               : p0n.x + p1n.x + p2n.x + bn2.x);
                float gxr = q ? gr.y : gr.x;
                float gxz = q ? gz.y : gz.x;
                float gxn = q ? gn.y : gn.x;
                float hol = q ? hreg[q2].y : hreg[q2].x;

                float r = 1.f / (1.f + expf(-(gxr + ghr)));
                float z = 1.f / (1.f + expf(-(gxz + ghz)));
                float n = tanhf(gxn + r * ghn);
                hnew[q] = n + z * (hol - n);
            }

            hreg[q2] = make_float2(hnew[0], hnew[1]);

            __nv_bfloat162 h2 = __floats2bfloat162_rn(hnew[0], hnew[1]);
            float r0 = hnew[0] - __bfloat162float(__low2bfloat16(h2));
            float r1 = hnew[1] - __bfloat162float(__high2bfloat16(h2));
            __nv_bfloat162 l2v = __floats2bfloat162_rn(r0, r1);

            *(__nv_bfloat162*)(g_hhi + i) = h2;
            *(__nv_bfloat162*)(g_hlo + i) = l2v;

            size_t oidx = ((size_t)t * BB + b) * INK + (size_t)d2 * HH + jp;
            *(__nv_bfloat162*)(g_ahi + oidx) = h2;
            *(__nv_bfloat162*)(g_alo + oidx) = l2v;

            if (s == TT - 1) *(float2*)(hn_out + i) = hreg[q2];
        }

        grid_sync(phase);
    }
}

// ---------------------------------------------------------------------------
// Launch
// ---------------------------------------------------------------------------
extern "C" void kernel_launch(void* const* d_in, const int* in_sizes, int n_in,
                              void* d_out, int out_size) {
    const float* x   = (const float*)d_in[0];  // [T, B, 2048]
    const float* h0  = (const float*)d_in[1];  // [6, B, H]
    const float* wih = (const float*)d_in[2];  // [3, 2, 3072, 2048]
    const float* whh = (const float*)d_in[3];  // [3, 2, 3072, 1024]
    const float* bih = (const float*)d_in[4];  // [3, 2, 3072]
    const float* bhh = (const float*)d_in[5];  // [3, 2, 3072]
    float* out = (float*)d_out;                // [6, B, H]

    __nv_bfloat16 *ahi, *alo, *whi, *wlo, *uhi, *ulo;
    cudaGetSymbolAddress((void**)&ahi, g_ahi);
    cudaGetSymbolAddress((void**)&alo, g_alo);
    cudaGetSymbolAddress((void**)&whi, g_whi);
    cudaGetSymbolAddress((void**)&wlo, g_wlo);
    cudaGetSymbolAddress((void**)&uhi, g_uhi);
    cudaGetSymbolAddress((void**)&ulo, g_ulo);

    cudaFuncSetAttribute(gx_mma_kernel,
                         cudaFuncAttributeMaxDynamicSharedMemorySize, GX_SMEM);
    cudaFuncSetAttribute(gru_recurrent_kernel,
                         cudaFuncAttributeMaxDynamicSharedMemorySize, RC_SMEM);

    {   // split w_ih
        size_t n4 = (size_t)6 * IN3H * INK / 4;
        split_bf16_kernel<<<(unsigned)((n4 + 255) / 256), 256>>>(wih, whi, wlo, n4);
    }
    {   // split w_hh
        size_t n4 = (size_t)6 * IN3H * HH / 4;
        split_bf16_kernel<<<(unsigned)((n4 + 255) / 256), 256>>>(whh, uhi, ulo, n4);
    }
    {   // split x (layer-0 input)
        size_t n4 = (size_t)GX_M * INK / 4;
        split_bf16_kernel<<<(unsigned)((n4 + 255) / 256), 256>>>(x, ahi, alo, n4);
    }

    for (int l = 0; l < 3; l++) {
        gx_mma_kernel<<<dim3(IN3H / 128, GX_M / 128, 2), 256, GX_SMEM>>>(
            whi + (size_t)l * 2 * IN3H * INK,
            wlo + (size_t)l * 2 * IN3H * INK,
            bih + (size_t)l * 2 * IN3H);

        gru_recurrent_kernel<<<REC_BLOCKS, REC_THREADS, RC_SMEM>>>(
            h0  + (size_t)l * 2 * BB * HH,
            uhi + (size_t)l * 2 * IN3H * HH,
            ulo + (size_t)l * 2 * IN3H * HH,
            bhh + (size_t)l * 2 * IN3H,
            out + (size_t)l * 2 * BB * HH);
    }
}

// round 15
// speedup vs baseline: 1.2159x; 1.0703x over previous
#include <cuda_runtime.h>
#include <cuda_bf16.h>
#include <math.h>
#include <stdint.h>
#include <stddef.h>

// Problem constants
#define TT 256
#define BB 64
#define HH 1024
#define IN3H 3072          // 3*H
#define INK 2048           // input width of every layer (IN = 2H)
#define GX_M (TT * BB)     // 16384
#define GXSZ ((size_t)GX_M * IN3H)

#define REC_BLOCKS 144     // 2 dirs * 24 N-tiles(128) * 3 K-splits
#define REC_THREADS 256

// ---------------------------------------------------------------------------
// Scratch (device globals -- no allocation allowed)
// ---------------------------------------------------------------------------
__device__ float g_gx[2 * GXSZ];                        // input gates (fp32)
__device__ float g_ghp[3][2][(size_t)BB * IN3H];        // hidden-gate partials
__device__ __nv_bfloat16 g_hhi[2 * BB * HH];            // hidden state hi/lo
__device__ __nv_bfloat16 g_hlo[2 * BB * HH];
__device__ __nv_bfloat16 g_ahi[(size_t)GX_M * INK];     // layer input hi/lo
__device__ __nv_bfloat16 g_alo[(size_t)GX_M * INK];
__device__ __nv_bfloat16 g_whi[(size_t)6 * IN3H * INK]; // w_ih hi/lo
__device__ __nv_bfloat16 g_wlo[(size_t)6 * IN3H * INK];
__device__ __nv_bfloat16 g_uhi[(size_t)6 * IN3H * HH];  // w_hh hi/lo
__device__ __nv_bfloat16 g_ulo[(size_t)6 * IN3H * HH];

// Monotonic arrival counter (zeroed by cudaMemsetAsync before each rec launch)
__device__ unsigned g_bar_ctr;

// ---------------------------------------------------------------------------
// Baseline-PTX helpers (valid on compute_103)
// ---------------------------------------------------------------------------
__device__ __forceinline__ uint32_t smem_u32(const void* p) {
    uint32_t a;
    asm("{ .reg .u64 t; cvta.to.shared.u64 t, %1; cvt.u32.u64 %0, t; }"
        : "=r"(a) : "l"(p));
    return a;
}

__device__ __forceinline__ void cp_async16(uint32_t dst, const void* src) {
    asm volatile("cp.async.cg.shared.global [%0], [%1], 16;"
                 :: "r"(dst), "l"(src) : "memory");
}
#define CP_COMMIT() asm volatile("cp.async.commit_group;" ::: "memory")
#define CP_WAIT0()  asm volatile("cp.async.wait_group 0;" ::: "memory")
#define CP_WAIT1()  asm volatile("cp.async.wait_group 1;" ::: "memory")

__device__ __forceinline__ void ldsm4(uint32_t* r, uint32_t addr) {
    asm volatile("ldmatrix.sync.aligned.m8n8.x4.shared.b16 {%0,%1,%2,%3}, [%4];"
                 : "=r"(r[0]), "=r"(r[1]), "=r"(r[2]), "=r"(r[3]) : "r"(addr));
}

__device__ __forceinline__ void mma_bf16(float* c, const uint32_t* a,
                                         uint32_t b0, uint32_t b1) {
    asm("mma.sync.aligned.m16n8k16.row.col.f32.bf16.bf16.f32 "
        "{%0,%1,%2,%3}, {%4,%5,%6,%7}, {%8,%9}, {%0,%1,%2,%3};"
        : "+f"(c[0]), "+f"(c[1]), "+f"(c[2]), "+f"(c[3])
        : "r"(a[0]), "r"(a[1]), "r"(a[2]), "r"(a[3]), "r"(b0), "r"(b1));
}

__device__ __forceinline__ void prefetch_l2(const void* p) {
    asm volatile("prefetch.global.L2 [%0];" :: "l"(p));
}

// REDG arrival: fire-and-forget increment (no ATOMG return-trip chain)
__device__ __forceinline__ void red_add(unsigned* ctr) {
    asm volatile("red.global.add.u32 [%0], %1;" :: "l"(ctr), "r"(1u) : "memory");
}

// ---------------------------------------------------------------------------
// Split fp32 -> (bf16 hi, bf16 lo)
// ---------------------------------------------------------------------------
__device__ __forceinline__ uint32_t pack2bf(float a, float b) {
    __nv_bfloat162 t = __floats2bfloat162_rn(a, b);
    return *(uint32_t*)&t;
}

__global__ __launch_bounds__(256) void split_bf16_kernel(
    const float* __restrict__ src, __nv_bfloat16* __restrict__ hi,
    __nv_bfloat16* __restrict__ lo, size_t n4) {
    size_t i = (size_t)blockIdx.x * 256 + threadIdx.x;
    if (i >= n4) return;
    float4 v = ((const float4*)src)[i];
    float h0 = __bfloat162float(__float2bfloat16(v.x));
    float h1 = __bfloat162float(__float2bfloat16(v.y));
    float h2 = __bfloat162float(__float2bfloat16(v.z));
    float h3 = __bfloat162float(__float2bfloat16(v.w));
    uint2 hv, lv;
    hv.x = pack2bf(v.x, v.y);           hv.y = pack2bf(v.z, v.w);
    lv.x = pack2bf(v.x - h0, v.y - h1); lv.y = pack2bf(v.z - h2, v.w - h3);
    ((uint2*)hi)[i] = hv;
    ((uint2*)lo)[i] = lv;
}

// ---------------------------------------------------------------------------
// gx GEMM -- VERBATIM R13/R14 (75.2% tensor): 128x128 tile, k-chunk 32,
// XOR-swizzled 64B rows, 3-stage cp.async, 2 CTAs/SM, one sync per chunk.
// ---------------------------------------------------------------------------
#define GX_STAGE 32768
#define GX_SMEM  (3 * GX_STAGE)
#define GX_NCHUNK 64

__device__ __forceinline__ void gx_load(uint32_t sm, int bm, int bn, int k0,
                                        int tid, const __nv_bfloat16* Bhi,
                                        const __nv_bfloat16* Blo) {
#pragma unroll
    for (int it = 0; it < 8; it++) {
        int idx = it * 256 + tid;        // 0..2047
        int mat = idx >> 9;              // constant per it
        int r   = (idx >> 2) & 127;
        int seg = idx & 3;
        int co  = k0 + seg * 8;
        uint32_t dst = sm + mat * 8192 + r * 64
                       + (uint32_t)((seg ^ ((r >> 1) & 3)) * 16);
        const __nv_bfloat16* src;
        if (mat == 0)      src = g_ahi + (size_t)(bm + r) * INK + co;
        else if (mat == 1) src = g_alo + (size_t)(bm + r) * INK + co;
        else if (mat == 2) src = Bhi   + (size_t)(bn + r) * INK + co;
        else               src = Blo   + (size_t)(bn + r) * INK + co;
        cp_async16(dst, src);
    }
}

__global__ __launch_bounds__(256, 2) void gx_mma_kernel(
    const __nv_bfloat16* __restrict__ Whi,
    const __nv_bfloat16* __restrict__ Wlo,
    const float* __restrict__ bias)
{
    extern __shared__ char smem[];
    const uint32_t sb = smem_u32(smem);
    const int tid = threadIdx.x, wid = tid >> 5, lid = tid & 31;
    const int bn = blockIdx.x * 128;
    const int bm = blockIdx.y * 128;
    const int d  = blockIdx.z;

    const __nv_bfloat16* Bhi = Whi + (size_t)d * IN3H * INK;
    const __nv_bfloat16* Blo = Wlo + (size_t)d * IN3H * INK;
    const float* bptr = bias + d * IN3H;
    float* C = g_gx + (size_t)d * GXSZ;

    const uint32_t key = (uint32_t)(((lid & 7) >> 1) & 3);
    const uint32_t abase = (uint32_t)(((wid & 3) * 32 + (lid & 7)
                                       + ((lid >> 3) & 1) * 8) * 64);
    const uint32_t ach = (uint32_t)((lid >> 4) & 1);
    const uint32_t bbase = (uint32_t)(((wid >> 2) * 64 + (lid & 7)
                                       + ((lid >> 4) & 1) * 8) * 64);
    const uint32_t bch = (uint32_t)((lid >> 3) & 1);

    float acc[2][8][4];
#pragma unroll
    for (int i = 0; i < 2; i++)
#pragma unroll
        for (int j = 0; j < 8; j++)
#pragma unroll
            for (int q = 0; q < 4; q++) acc[i][j][q] = 0.f;

    gx_load(sb,            bm, bn,  0, tid, Bhi, Blo); CP_COMMIT();
    gx_load(sb + GX_STAGE, bm, bn, 32, tid, Bhi, Blo); CP_COMMIT();

    for (int c = 0; c < GX_NCHUNK; c++) {
        if (c + 1 < GX_NCHUNK) { CP_WAIT1(); } else { CP_WAIT0(); }
        __syncthreads();
        if (c + 2 < GX_NCHUNK) {
            gx_load(sb + ((c + 2) % 3) * GX_STAGE, bm, bn, (c + 2) * 32,
                    tid, Bhi, Blo);
            CP_COMMIT();
        }
        const uint32_t st = sb + (c % 3) * GX_STAGE;

#pragma unroll
        for (int kk = 0; kk < 2; kk++) {
            const uint32_t ak = ((kk * 2 + ach) ^ key) * 16;
            const uint32_t bk = ((kk * 2 + bch) ^ key) * 16;
            uint32_t ah[2][4], al[2][4];
            ldsm4(ah[0], st + abase + ak);
            ldsm4(ah[1], st + abase + 1024 + ak);
            ldsm4(al[0], st + 8192 + abase + ak);
            ldsm4(al[1], st + 8192 + abase + 1024 + ak);
#pragma unroll
            for (int g = 0; g < 4; g++) {
                uint32_t bh[4], bl[4];
                ldsm4(bh, st + 16384 + bbase + g * 1024 + bk);
                ldsm4(bl, st + 24576 + bbase + g * 1024 + bk);
                mma_bf16(acc[0][2 * g],     ah[0], bh[0], bh[1]);
                mma_bf16(acc[0][2 * g + 1], ah[0], bh[2], bh[3]);
                mma_bf16(acc[1][2 * g],     ah[1], bh[0], bh[1]);
                mma_bf16(acc[1][2 * g + 1], ah[1], bh[2], bh[3]);
                mma_bf16(acc[0][2 * g],     ah[0], bl[0], bl[1]);
                mma_bf16(acc[0][2 * g + 1], ah[0], bl[2], bl[3]);
                mma_bf16(acc[1][2 * g],     ah[1], bl[0], bl[1]);
                mma_bf16(acc[1][2 * g + 1], ah[1], bl[2], bl[3]);
                mma_bf16(acc[0][2 * g],     al[0], bh[0], bh[1]);
                mma_bf16(acc[0][2 * g + 1], al[0], bh[2], bh[3]);
                mma_bf16(acc[1][2 * g],     al[1], bh[0], bh[1]);
                mma_bf16(acc[1][2 * g + 1], al[1], bh[2], bh[3]);
            }
        }
    }

    const int lr = lid >> 2;
    const int lc = (lid & 3) * 2;
#pragma unroll
    for (int mt = 0; mt < 2; mt++) {
        const int row = bm + (wid & 3) * 32 + mt * 16 + lr;
#pragma unroll
        for (int nt = 0; nt < 8; nt++) {
            const int col = bn + (wid >> 2) * 64 + nt * 8 + lc;
            float b0 = bptr[col], b1 = bptr[col + 1];
            float* c = acc[mt][nt];
            C[(size_t)row * IN3H + col]           = c[0] + b0;
            C[(size_t)row * IN3H + col + 1]       = c[1] + b1;
            C[(size_t)(row + 8) * IN3H + col]     = c[2] + b0;
            C[(size_t)(row + 8) * IN3H + col + 1] = c[3] + b1;
        }
    }
}

// ---------------------------------------------------------------------------
// R15 grid barrier: REDG arrival + monotonic-target polling.
// Arrival is fire-and-forget (~0.854 cyc/lane vs ~27 cyc/serialized ATOMG),
// so the last arrival lands ~150 cyc after the first instead of ~3900.
// g_bar_ctr is zeroed by cudaMemsetAsync before each launch.
// ---------------------------------------------------------------------------
__device__ __forceinline__ void grid_sync(unsigned& ncalls) {
    __threadfence();
    __syncthreads();
    ncalls++;
    if (threadIdx.x == 0) {
        red_add(&g_bar_ctr);
        const unsigned target = ncalls * REC_BLOCKS;
        while (*(volatile unsigned*)&g_bar_ctr < target) { }
        __threadfence();
    }
    __syncthreads();
}

// ---------------------------------------------------------------------------
// Persistent recurrent kernel -- R14 structure (3-stage swizzled A-path,
// h-in-registers, gx L2 prefetch); R15 swaps in the REDG barrier and skips
// the dead final sync.
// smem map (dynamic, 204800 B):
//   A stages: [3][ hi 4096 | lo 4096 ]              @ 0      (24576)
//   B hi:     [chunk][128 rows][64 B, swizzled]     @ 24576  (90112)
//   B lo:                                           @ 114688 (90112)
// ---------------------------------------------------------------------------
#define RC_SB_BHI 24576
#define RC_SB_BLO 114688
#define RC_SMEM   204800

__device__ __forceinline__ void rec_loadA(uint32_t stage,
                                          const __nv_bfloat16* hhi,
                                          const __nv_bfloat16* hlo,
                                          int k0, int tid) {
    int r   = tid >> 2;          // 0..63
    int seg = tid & 3;
    int co  = k0 + seg * 8;
    uint32_t off = (uint32_t)(r * 64 + ((seg ^ ((r >> 1) & 3)) * 16));
    cp_async16(stage + off,        hhi + (size_t)r * HH + co);
    cp_async16(stage + 4096 + off, hlo + (size_t)r * HH + co);
}

__global__ __launch_bounds__(REC_THREADS)
void gru_recurrent_kernel(const float* __restrict__ h0_layer,    // [2,B,H]
                          const __nv_bfloat16* __restrict__ Uhi, // [2,3H,H]
                          const __nv_bfloat16* __restrict__ Ulo,
                          const float* __restrict__ bhh_layer,   // [2,3H]
                          float* __restrict__ hn_out)            // [2,B,H]
{
    extern __shared__ char smem[];
    const uint32_t sb = smem_u32(smem);
    const int bid = blockIdx.x, tid = threadIdx.x;
    const int wid = tid >> 5, lid = tid & 31;
    const int d   = bid / 72;
    const int rem = bid % 72;
    const int nt  = rem / 3;            // 0..23 -> 128 gh columns each
    const int ks  = rem % 3;            // K split
    const int bn0  = nt * 128;
    const int kbeg = ks * 352;          // {0, 352, 704}
    const int nc   = (ks == 2) ? 10 : 11;   // chunks of 32 k

    const __nv_bfloat16* Whi = Uhi + (size_t)d * IN3H * HH;
    const __nv_bfloat16* Wlo = Ulo + (size_t)d * IN3H * HH;
    float* Pout = g_ghp[ks][d];

    unsigned ncalls = 0;   // local barrier-call count (counter zeroed host-side)

    // ---- One-time weight preload into resident smem (swizzled 64B rows) ----
    for (int idx = tid; idx < nc * 512; idx += REC_THREADS) {
        int chunk = idx >> 9;
        int r     = (idx >> 2) & 127;
        int seg   = idx & 3;
        int col   = kbeg + chunk * 32 + seg * 8;
        uint32_t dst = (uint32_t)(chunk * 8192 + r * 64
                                  + ((seg ^ ((r >> 1) & 3)) * 16));
        cp_async16(sb + RC_SB_BHI + dst, Whi + (size_t)(bn0 + r) * HH + col);
        cp_async16(sb + RC_SB_BLO + dst, Wlo + (size_t)(bn0 + r) * HH + col);
    }
    CP_COMMIT();
    CP_WAIT0();

    // Prologue: split h0 into bf16 hi/lo state buffers
    for (int i = bid * REC_THREADS + tid; i < 2 * BB * HH;
         i += REC_BLOCKS * REC_THREADS) {
        float v = h0_layer[i];
        __nv_bfloat16 hi = __float2bfloat16(v);
        g_hhi[i] = hi;
        g_hlo[i] = __float2bfloat16(v - __bfloat162float(hi));
    }

    // Per-thread gate-state registers (mapping p -> (d2,b,jp) step-invariant)
    float2 hreg[2];
    int pidx[2], pcnt = 0;
    {
        int p = bid * REC_THREADS + tid;
#pragma unroll
        for (int q = 0; q < 2; q++) {
            if (p < 65536) {
                pidx[pcnt] = p;
                const int d2 = p >> 15;
                const int rm = p & 32767;
                const int b  = rm >> 9;
                const int jp = (rm & 511) << 1;
                const int i  = d2 * BB * HH + b * HH + jp;
                hreg[pcnt] = *(const float2*)(h0_layer + i);
                pcnt++;
            }
            p += REC_BLOCKS * REC_THREADS;
        }
    }
    grid_sync(ncalls);

    // A ldmatrix (64B swizzled rows): warp m = (wid&1)*32
    const uint32_t key   = (uint32_t)(((lid & 7) >> 1) & 3);
    const uint32_t abase = (uint32_t)(((wid & 1) * 32 + (lid & 7)
                                       + ((lid >> 3) & 1) * 8) * 64);
    const uint32_t ach   = (uint32_t)((lid >> 4) & 1);
    // B ldmatrix (64B rows, XOR swizzle): warp n = (wid>>1)*32
    const int brow0 = (wid >> 1) * 32 + (lid & 7) + ((lid >> 4) & 1) * 8;
    const int bkey  = (brow0 >> 1) & 3;
    const int lb3   = (lid >> 3) & 1;
    const uint32_t bseg0 = (uint32_t)(((0 + lb3) ^ bkey) * 16);
    const uint32_t bseg1 = (uint32_t)(((2 + lb3) ^ bkey) * 16);
    const uint32_t bbase = (uint32_t)(brow0 * 64);

    const __nv_bfloat16* hhi = g_hhi + (size_t)d * BB * HH;
    const __nv_bfloat16* hlo = g_hlo + (size_t)d * BB * HH;

    for (int s = 0; s < TT; s++) {
        float acc[2][4][4];
#pragma unroll
        for (int i = 0; i < 2; i++)
#pragma unroll
            for (int j = 0; j < 4; j++)
#pragma unroll
                for (int q = 0; q < 4; q++) acc[i][j][q] = 0.f;

        // Prologue: chunks 0,1 into stages 0,1
        rec_loadA(sb,        hhi, hlo, kbeg,      tid); CP_COMMIT();
        rec_loadA(sb + 8192, hhi, hlo, kbeg + 32, tid); CP_COMMIT();

        // Prefetch this step's gx rows into L2 (R11 win)
        {
            const int ln = bid * REC_THREADS + tid;
            if (ln < 6144) {
                prefetch_l2(g_gx + (size_t)s * BB * IN3H + (size_t)ln * 32);
            } else if (ln < 12288) {
                prefetch_l2(g_gx + GXSZ + (size_t)(TT - 1 - s) * BB * IN3H
                            + (size_t)(ln - 6144) * 32);
            }
        }

        for (int c = 0; c < nc; c++) {
            if (c + 1 < nc) { CP_WAIT1(); } else { CP_WAIT0(); }
            __syncthreads();
            if (c + 2 < nc) {
                rec_loadA(sb + ((c + 2) % 3) * 8192, hhi, hlo,
                          kbeg + (c + 2) * 32, tid);
                CP_COMMIT();
            }
            const uint32_t stA  = sb + (c % 3) * 8192;
            const uint32_t stBh = sb + RC_SB_BHI + c * 8192 + bbase;
            const uint32_t stBl = sb + RC_SB_BLO + c * 8192 + bbase;

#pragma unroll
            for (int kk = 0; kk < 2; kk++) {
                const uint32_t ak  = ((kk * 2 + ach) ^ key) * 16;
                const uint32_t bso = kk ? bseg1 : bseg0;
                uint32_t ah[2][4], al[2][4], bh[2][4], bl[2][4];
                ldsm4(ah[0], stA + abase + ak);
                ldsm4(ah[1], stA + abase + 1024 + ak);       // +16 rows
                ldsm4(al[0], stA + 4096 + abase + ak);
                ldsm4(al[1], stA + 4096 + abase + 1024 + ak);
                ldsm4(bh[0], stBh + bso);
                ldsm4(bh[1], stBh + 1024 + bso);
                ldsm4(bl[0], stBl + bso);
                ldsm4(bl[1], stBl + 1024 + bso);
#pragma unroll
                for (int mt = 0; mt < 2; mt++)
#pragma unroll
                    for (int g = 0; g < 2; g++) {
                        mma_bf16(acc[mt][2 * g],     ah[mt], bh[g][0], bh[g][1]);
                        mma_bf16(acc[mt][2 * g + 1], ah[mt], bh[g][2], bh[g][3]);
                    }
#pragma unroll
                for (int mt = 0; mt < 2; mt++)
#pragma unroll
                    for (int g = 0; g < 2; g++) {
                        mma_bf16(acc[mt][2 * g],     ah[mt], bl[g][0], bl[g][1]);
                        mma_bf16(acc[mt][2 * g + 1], ah[mt], bl[g][2], bl[g][3]);
                    }
#pragma unroll
                for (int mt = 0; mt < 2; mt++)
#pragma unroll
                    for (int g = 0; g < 2; g++) {
                        mma_bf16(acc[mt][2 * g],     al[mt], bh[g][0], bh[g][1]);
                        mma_bf16(acc[mt][2 * g + 1], al[mt], bh[g][2], bh[g][3]);
                    }
            }
        }

        // Epilogue: write 64x128 partial tile
        {
            const int lr = lid >> 2;
            const int lc = (lid & 3) * 2;
#pragma unroll
            for (int mt = 0; mt < 2; mt++) {
                const int row = (wid & 1) * 32 + mt * 16 + lr;
#pragma unroll
                for (int j = 0; j < 4; j++) {
                    const int col = bn0 + (wid >> 1) * 32 + j * 8 + lc;
                    float* c = acc[mt][j];
                    Pout[(size_t)row * IN3H + col]           = c[0];
                    Pout[(size_t)row * IN3H + col + 1]       = c[1];
                    Pout[(size_t)(row + 8) * IN3H + col]     = c[2];
                    Pout[(size_t)(row + 8) * IN3H + col + 1] = c[3];
                }
            }
        }

        grid_sync(ncalls);

        // Gate phase -- float2 vectorized; h state in registers
#pragma unroll
        for (int q2 = 0; q2 < 2; q2++) {
            if (q2 >= pcnt) break;
            const int p  = pidx[q2];
            const int d2 = p >> 15;
            const int rm = p & 32767;
            const int b  = rm >> 9;
            const int jp = (rm & 511) << 1;
            const int i  = d2 * BB * HH + b * HH + jp;
            const int t  = d2 ? (TT - 1 - s) : s;

            const float* gxp = g_gx + (size_t)d2 * GXSZ + ((size_t)t * BB + b) * IN3H;
            const float* P0 = g_ghp[0][d2] + (size_t)b * IN3H;
            const float* P1 = g_ghp[1][d2] + (size_t)b * IN3H;
            const float* P2 = g_ghp[2][d2] + (size_t)b * IN3H;
            const float* bias2 = bhh_layer + d2 * IN3H;

            float2 gr  = *(const float2*)(gxp + jp);
            float2 gz  = *(const float2*)(gxp + HH + jp);
            float2 gn  = *(const float2*)(gxp + 2 * HH + jp);
            float2 p0r = *(const float2*)(P0 + jp);
            float2 p0z = *(const float2*)(P0 + HH + jp);
            float2 p0n = *(const float2*)(P0 + 2 * HH + jp);
            float2 p1r = *(const float2*)(P1 + jp);
            float2 p1z = *(const float2*)(P1 + HH + jp);
            float2 p1n = *(const float2*)(P1 + 2 * HH + jp);
            float2 p2r = *(const float2*)(P2 + jp);
            float2 p2z = *(const float2*)(P2 + HH + jp);
            float2 p2n = *(const float2*)(P2 + 2 * HH + jp);
            float2 br  = *(const float2*)(bias2 + jp);
            float2 bz  = *(const float2*)(bias2 + HH + jp);
            float2 bn2 = *(const float2*)(bias2 + 2 * HH + jp);

            float hnew[2];
#pragma unroll
            for (int q = 0; q < 2; q++) {
                float ghr = (q ? p0r.y + p1r.y + p2r.y + br.y
                               : p0r.x + p1r.x + p2r.x + br.x);
                float ghz = (q ? p0z.y + p1z.y + p2z.y + bz.y
                               : p0z.x + p1z.x + p2z.x + bz.x);
                float ghn = (q ? p0n.y + p1n.y + p2n.y + bn2.y
                               : p0n.x + p1n.x + p2n.x + bn2.x);
                float gxr = q ? gr.y : gr.x;
                float gxz = q ? gz.y : gz.x;
                float gxn = q ? gn.y : gn.x;
                float hol = q ? hreg[q2].y : hreg[q2].x;

                float r = 1.f / (1.f + expf(-(gxr + ghr)));
                float z = 1.f / (1.f + expf(-(gxz + ghz)));
                float n = tanhf(gxn + r * ghn);
                hnew[q] = n + z * (hol - n);
            }

            hreg[q2] = make_float2(hnew[0], hnew[1]);

            __nv_bfloat162 h2 = __floats2bfloat162_rn(hnew[0], hnew[1]);
            float r0 = hnew[0] - __bfloat162float(__low2bfloat16(h2));
            float r1 = hnew[1] - __bfloat162float(__high2bfloat16(h2));
            __nv_bfloat162 l2v = __floats2bfloat162_rn(r0, r1);

            *(__nv_bfloat162*)(g_hhi + i) = h2;
            *(__nv_bfloat162*)(g_hlo + i) = l2v;

            size_t oidx = ((size_t)t * BB + b) * INK + (size_t)d2 * HH + jp;
            *(__nv_bfloat162*)(g_ahi + oidx) = h2;
            *(__nv_bfloat162*)(g_alo + oidx) = l2v;

            if (s == TT - 1) *(float2*)(hn_out + i) = hreg[q2];
        }

        if (s < TT - 1) grid_sync(ncalls);   // final sync is dead: kernel ends
    }
}

// ---------------------------------------------------------------------------
// Launch
// ---------------------------------------------------------------------------
extern "C" void kernel_launch(void* const* d_in, const int* in_sizes, int n_in,
                              void* d_out, int out_size) {
    const float* x   = (const float*)d_in[0];  // [T, B, 2048]
    const float* h0  = (const float*)d_in[1];  // [6, B, H]
    const float* wih = (const float*)d_in[2];  // [3, 2, 3072, 2048]
    const float* whh = (const float*)d_in[3];  // [3, 2, 3072, 1024]
    const float* bih = (const float*)d_in[4];  // [3, 2, 3072]
    const float* bhh = (const float*)d_in[5];  // [3, 2, 3072]
    float* out = (float*)d_out;                // [6, B, H]

    __nv_bfloat16 *ahi, *alo, *whi, *wlo, *uhi, *ulo;
    void* ctr;
    cudaGetSymbolAddress((void**)&ahi, g_ahi);
    cudaGetSymbolAddress((void**)&alo, g_alo);
    cudaGetSymbolAddress((void**)&whi, g_whi);
    cudaGetSymbolAddress((void**)&wlo, g_wlo);
    cudaGetSymbolAddress((void**)&uhi, g_uhi);
    cudaGetSymbolAddress((void**)&ulo, g_ulo);
    cudaGetSymbolAddress(&ctr, g_bar_ctr);

    cudaFuncSetAttribute(gx_mma_kernel,
                         cudaFuncAttributeMaxDynamicSharedMemorySize, GX_SMEM);
    cudaFuncSetAttribute(gru_recurrent_kernel,
                         cudaFuncAttributeMaxDynamicSharedMemorySize, RC_SMEM);

    {   // split w_ih
        size_t n4 = (size_t)6 * IN3H * INK / 4;
        split_bf16_kernel<<<(unsigned)((n4 + 255) / 256), 256>>>(wih, whi, wlo, n4);
    }
    {   // split w_hh
        size_t n4 = (size_t)6 * IN3H * HH / 4;
        split_bf16_kernel<<<(unsigned)((n4 + 255) / 256), 256>>>(whh, uhi, ulo, n4);
    }
    {   // split x (layer-0 input)
        size_t n4 = (size_t)GX_M * INK / 4;
        split_bf16_kernel<<<(unsigned)((n4 + 255) / 256), 256>>>(x, ahi, alo, n4);
    }

    for (int l = 0; l < 3; l++) {
        gx_mma_kernel<<<dim3(IN3H / 128, GX_M / 128, 2), 256, GX_SMEM>>>(
            whi + (size_t)l * 2 * IN3H * INK,
            wlo + (size_t)l * 2 * IN3H * INK,
            bih + (size_t)l * 2 * IN3H);

        cudaMemsetAsync(ctr, 0, sizeof(unsigned));   // reset barrier counter

        gru_recurrent_kernel<<<REC_BLOCKS, REC_THREADS, RC_SMEM>>>(
            h0  + (size_t)l * 2 * BB * HH,
            uhi + (size_t)l * 2 * IN3H * HH,
            ulo + (size_t)l * 2 * IN3H * HH,
            bhh + (size_t)l * 2 * IN3H,
            out + (size_t)l * 2 * BB * HH);
    }
}

// round 16
// speedup vs baseline: 1.2186x; 1.0022x over previous
#include <cuda_runtime.h>
#include <cuda_bf16.h>
#include <math.h>
#include <stdint.h>
#include <stddef.h>

// Problem constants
#define TT 256
#define BB 64
#define HH 1024
#define IN3H 3072          // 3*H
#define INK 2048           // input width of every layer (IN = 2H)
#define GX_M (TT * BB)     // 16384
#define GXSZ ((size_t)GX_M * IN3H)

#define REC_BLOCKS 144     // 2 dirs * 24 N-tiles(128) * 3 K-splits
#define REC_THREADS 256

// ---------------------------------------------------------------------------
// Scratch (device globals -- no allocation allowed)
// ---------------------------------------------------------------------------
__device__ float g_gx[2 * GXSZ];                        // input gates (fp32)
__device__ float g_ghp[3][2][(size_t)BB * IN3H];        // hidden-gate partials
__device__ __nv_bfloat16 g_hhi[2 * BB * HH];            // hidden state hi/lo
__device__ __nv_bfloat16 g_hlo[2 * BB * HH];
__device__ __nv_bfloat16 g_ahi[(size_t)GX_M * INK];     // layer input hi/lo
__device__ __nv_bfloat16 g_alo[(size_t)GX_M * INK];
__device__ __nv_bfloat16 g_whi[(size_t)6 * IN3H * INK]; // w_ih hi/lo
__device__ __nv_bfloat16 g_wlo[(size_t)6 * IN3H * INK];
__device__ __nv_bfloat16 g_uhi[(size_t)6 * IN3H * HH];  // w_hh hi/lo
__device__ __nv_bfloat16 g_ulo[(size_t)6 * IN3H * HH];

// Monotonic arrival counter (zeroed by cudaMemsetAsync before each rec launch)
__device__ unsigned g_bar_ctr;

// ---------------------------------------------------------------------------
// Baseline-PTX helpers (valid on compute_103)
// ---------------------------------------------------------------------------
__device__ __forceinline__ uint32_t smem_u32(const void* p) {
    uint32_t a;
    asm("{ .reg .u64 t; cvta.to.shared.u64 t, %1; cvt.u32.u64 %0, t; }"
        : "=r"(a) : "l"(p));
    return a;
}

__device__ __forceinline__ void cp_async16(uint32_t dst, const void* src) {
    asm volatile("cp.async.cg.shared.global [%0], [%1], 16;"
                 :: "r"(dst), "l"(src) : "memory");
}
#define CP_COMMIT() asm volatile("cp.async.commit_group;" ::: "memory")
#define CP_WAIT0()  asm volatile("cp.async.wait_group 0;" ::: "memory")
#define CP_WAIT1()  asm volatile("cp.async.wait_group 1;" ::: "memory")

__device__ __forceinline__ void ldsm4(uint32_t* r, uint32_t addr) {
    asm volatile("ldmatrix.sync.aligned.m8n8.x4.shared.b16 {%0,%1,%2,%3}, [%4];"
                 : "=r"(r[0]), "=r"(r[1]), "=r"(r[2]), "=r"(r[3]) : "r"(addr));
}

__device__ __forceinline__ void mma_bf16(float* c, const uint32_t* a,
                                         uint32_t b0, uint32_t b1) {
    asm("mma.sync.aligned.m16n8k16.row.col.f32.bf16.bf16.f32 "
        "{%0,%1,%2,%3}, {%4,%5,%6,%7}, {%8,%9}, {%0,%1,%2,%3};"
        : "+f"(c[0]), "+f"(c[1]), "+f"(c[2]), "+f"(c[3])
        : "r"(a[0]), "r"(a[1]), "r"(a[2]), "r"(a[3]), "r"(b0), "r"(b1));
}

__device__ __forceinline__ void prefetch_l2(const void* p) {
    asm volatile("prefetch.global.L2 [%0];" :: "l"(p));
}

// REDG arrival: fire-and-forget increment (no ATOMG return-trip chain)
__device__ __forceinline__ void red_add(unsigned* ctr) {
    asm volatile("red.global.add.u32 [%0], %1;" :: "l"(ctr), "r"(1u) : "memory");
}

// Fast gates (R7/R8-proven: rel_err 8.868e-6)
__device__ __forceinline__ float fsigmoid(float x) {
    return 1.f / (1.f + __expf(-x));
}
__device__ __forceinline__ float ftanh(float x) {
    return 1.f - 2.f / (__expf(2.f * x) + 1.f);
}

// ---------------------------------------------------------------------------
// Split fp32 -> (bf16 hi, bf16 lo)
// ---------------------------------------------------------------------------
__device__ __forceinline__ uint32_t pack2bf(float a, float b) {
    __nv_bfloat162 t = __floats2bfloat162_rn(a, b);
    return *(uint32_t*)&t;
}

__global__ __launch_bounds__(256) void split_bf16_kernel(
    const float* __restrict__ src, __nv_bfloat16* __restrict__ hi,
    __nv_bfloat16* __restrict__ lo, size_t n4) {
    size_t i = (size_t)blockIdx.x * 256 + threadIdx.x;
    if (i >= n4) return;
    float4 v = ((const float4*)src)[i];
    float h0 = __bfloat162float(__float2bfloat16(v.x));
    float h1 = __bfloat162float(__float2bfloat16(v.y));
    float h2 = __bfloat162float(__float2bfloat16(v.z));
    float h3 = __bfloat162float(__float2bfloat16(v.w));
    uint2 hv, lv;
    hv.x = pack2bf(v.x, v.y);           hv.y = pack2bf(v.z, v.w);
    lv.x = pack2bf(v.x - h0, v.y - h1); lv.y = pack2bf(v.z - h2, v.w - h3);
    ((uint2*)hi)[i] = hv;
    ((uint2*)lo)[i] = lv;
}

// ---------------------------------------------------------------------------
// gx GEMM -- VERBATIM R13/R15 (75.2% tensor): 128x128 tile, k-chunk 32,
// XOR-swizzled 64B rows, 3-stage cp.async, 2 CTAs/SM, one sync per chunk.
// ---------------------------------------------------------------------------
#define GX_STAGE 32768
#define GX_SMEM  (3 * GX_STAGE)
#define GX_NCHUNK 64

__device__ __forceinline__ void gx_load(uint32_t sm, int bm, int bn, int k0,
                                        int tid, const __nv_bfloat16* Bhi,
                                        const __nv_bfloat16* Blo) {
#pragma unroll
    for (int it = 0; it < 8; it++) {
        int idx = it * 256 + tid;        // 0..2047
        int mat = idx >> 9;              // constant per it
        int r   = (idx >> 2) & 127;
        int seg = idx & 3;
        int co  = k0 + seg * 8;
        uint32_t dst = sm + mat * 8192 + r * 64
                       + (uint32_t)((seg ^ ((r >> 1) & 3)) * 16);
        const __nv_bfloat16* src;
        if (mat == 0)      src = g_ahi + (size_t)(bm + r) * INK + co;
        else if (mat == 1) src = g_alo + (size_t)(bm + r) * INK + co;
        else if (mat == 2) src = Bhi   + (size_t)(bn + r) * INK + co;
        else               src = Blo   + (size_t)(bn + r) * INK + co;
        cp_async16(dst, src);
    }
}

__global__ __launch_bounds__(256, 2) void gx_mma_kernel(
    const __nv_bfloat16* __restrict__ Whi,
    const __nv_bfloat16* __restrict__ Wlo,
    const float* __restrict__ bias)
{
    extern __shared__ char smem[];
    const uint32_t sb = smem_u32(smem);
    const int tid = threadIdx.x, wid = tid >> 5, lid = tid & 31;
    const int bn = blockIdx.x * 128;
    const int bm = blockIdx.y * 128;
    const int d  = blockIdx.z;

    const __nv_bfloat16* Bhi = Whi + (size_t)d * IN3H * INK;
    const __nv_bfloat16* Blo = Wlo + (size_t)d * IN3H * INK;
    const float* bptr = bias + d * IN3H;
    float* C = g_gx + (size_t)d * GXSZ;

    const uint32_t key = (uint32_t)(((lid & 7) >> 1) & 3);
    const uint32_t abase = (uint32_t)(((wid & 3) * 32 + (lid & 7)
                                       + ((lid >> 3) & 1) * 8) * 64);
    const uint32_t ach = (uint32_t)((lid >> 4) & 1);
    const uint32_t bbase = (uint32_t)(((wid >> 2) * 64 + (lid & 7)
                                       + ((lid >> 4) & 1) * 8) * 64);
    const uint32_t bch = (uint32_t)((lid >> 3) & 1);

    float acc[2][8][4];
#pragma unroll
    for (int i = 0; i < 2; i++)
#pragma unroll
        for (int j = 0; j < 8; j++)
#pragma unroll
            for (int q = 0; q < 4; q++) acc[i][j][q] = 0.f;

    gx_load(sb,            bm, bn,  0, tid, Bhi, Blo); CP_COMMIT();
    gx_load(sb + GX_STAGE, bm, bn, 32, tid, Bhi, Blo); CP_COMMIT();

    for (int c = 0; c < GX_NCHUNK; c++) {
        if (c + 1 < GX_NCHUNK) { CP_WAIT1(); } else { CP_WAIT0(); }
        __syncthreads();
        if (c + 2 < GX_NCHUNK) {
            gx_load(sb + ((c + 2) % 3) * GX_STAGE, bm, bn, (c + 2) * 32,
                    tid, Bhi, Blo);
            CP_COMMIT();
        }
        const uint32_t st = sb + (c % 3) * GX_STAGE;

#pragma unroll
        for (int kk = 0; kk < 2; kk++) {
            const uint32_t ak = ((kk * 2 + ach) ^ key) * 16;
            const uint32_t bk = ((kk * 2 + bch) ^ key) * 16;
            uint32_t ah[2][4], al[2][4];
            ldsm4(ah[0], st + abase + ak);
            ldsm4(ah[1], st + abase + 1024 + ak);
            ldsm4(al[0], st + 8192 + abase + ak);
            ldsm4(al[1], st + 8192 + abase + 1024 + ak);
#pragma unroll
            for (int g = 0; g < 4; g++) {
                uint32_t bh[4], bl[4];
                ldsm4(bh, st + 16384 + bbase + g * 1024 + bk);
                ldsm4(bl, st + 24576 + bbase + g * 1024 + bk);
                mma_bf16(acc[0][2 * g],     ah[0], bh[0], bh[1]);
                mma_bf16(acc[0][2 * g + 1], ah[0], bh[2], bh[3]);
                mma_bf16(acc[1][2 * g],     ah[1], bh[0], bh[1]);
                mma_bf16(acc[1][2 * g + 1], ah[1], bh[2], bh[3]);
                mma_bf16(acc[0][2 * g],     ah[0], bl[0], bl[1]);
                mma_bf16(acc[0][2 * g + 1], ah[0], bl[2], bl[3]);
                mma_bf16(acc[1][2 * g],     ah[1], bl[0], bl[1]);
                mma_bf16(acc[1][2 * g + 1], ah[1], bl[2], bl[3]);
                mma_bf16(acc[0][2 * g],     al[0], bh[0], bh[1]);
                mma_bf16(acc[0][2 * g + 1], al[0], bh[2], bh[3]);
                mma_bf16(acc[1][2 * g],     al[1], bh[0], bh[1]);
                mma_bf16(acc[1][2 * g + 1], al[1], bh[2], bh[3]);
            }
        }
    }

    const int lr = lid >> 2;
    const int lc = (lid & 3) * 2;
#pragma unroll
    for (int mt = 0; mt < 2; mt++) {
        const int row = bm + (wid & 3) * 32 + mt * 16 + lr;
#pragma unroll
        for (int nt = 0; nt < 8; nt++) {
            const int col = bn + (wid >> 2) * 64 + nt * 8 + lc;
            float b0 = bptr[col], b1 = bptr[col + 1];
            float* c = acc[mt][nt];
            C[(size_t)row * IN3H + col]           = c[0] + b0;
            C[(size_t)row * IN3H + col + 1]       = c[1] + b1;
            C[(size_t)(row + 8) * IN3H + col]     = c[2] + b0;
            C[(size_t)(row + 8) * IN3H + col + 1] = c[3] + b1;
        }
    }
}

// ---------------------------------------------------------------------------
// R15 grid barrier: REDG arrival + monotonic-target polling.
// ---------------------------------------------------------------------------
__device__ __forceinline__ void grid_sync(unsigned& ncalls) {
    __threadfence();
    __syncthreads();
    ncalls++;
    if (threadIdx.x == 0) {
        red_add(&g_bar_ctr);
        const unsigned target = ncalls * REC_BLOCKS;
        while (*(volatile unsigned*)&g_bar_ctr < target) { }
        __threadfence();
    }
    __syncthreads();
}

// ---------------------------------------------------------------------------
// Persistent recurrent kernel -- R15 structure; R16 adds:
//   (a) step-invariant gate operands (bias, partial pointers) hoisted to regs
//   (b) fast __expf gates (R7-proven numerics)
//   (c) emit_a flag: last layer skips dead g_ahi/g_alo stores
// smem map (dynamic, 204800 B): A stages [3][hi 4096|lo 4096] @0;
//   B hi @24576 (90112); B lo @114688 (90112)
// ---------------------------------------------------------------------------
#define RC_SB_BHI 24576
#define RC_SB_BLO 114688
#define RC_SMEM   204800

__device__ __forceinline__ void rec_loadA(uint32_t stage,
                                          const __nv_bfloat16* hhi,
                                          const __nv_bfloat16* hlo,
                                          int k0, int tid) {
    int r   = tid >> 2;          // 0..63
    int seg = tid & 3;
    int co  = k0 + seg * 8;
    uint32_t off = (uint32_t)(r * 64 + ((seg ^ ((r >> 1) & 3)) * 16));
    cp_async16(stage + off,        hhi + (size_t)r * HH + co);
    cp_async16(stage + 4096 + off, hlo + (size_t)r * HH + co);
}

__global__ __launch_bounds__(REC_THREADS)
void gru_recurrent_kernel(const float* __restrict__ h0_layer,    // [2,B,H]
                          const __nv_bfloat16* __restrict__ Uhi, // [2,3H,H]
                          const __nv_bfloat16* __restrict__ Ulo,
                          const float* __restrict__ bhh_layer,   // [2,3H]
                          float* __restrict__ hn_out,            // [2,B,H]
                          int emit_a)                            // 0 on last layer
{
    extern __shared__ char smem[];
    const uint32_t sb = smem_u32(smem);
    const int bid = blockIdx.x, tid = threadIdx.x;
    const int wid = tid >> 5, lid = tid & 31;
    const int d   = bid / 72;
    const int rem = bid % 72;
    const int nt  = rem / 3;            // 0..23 -> 128 gh columns each
    const int ks  = rem % 3;            // K split
    const int bn0  = nt * 128;
    const int kbeg = ks * 352;          // {0, 352, 704}
    const int nc   = (ks == 2) ? 10 : 11;   // chunks of 32 k

    const __nv_bfloat16* Whi = Uhi + (size_t)d * IN3H * HH;
    const __nv_bfloat16* Wlo = Ulo + (size_t)d * IN3H * HH;
    float* Pout = g_ghp[ks][d];

    unsigned ncalls = 0;

    // ---- One-time weight preload into resident smem (swizzled 64B rows) ----
    for (int idx = tid; idx < nc * 512; idx += REC_THREADS) {
        int chunk = idx >> 9;
        int r     = (idx >> 2) & 127;
        int seg   = idx & 3;
        int col   = kbeg + chunk * 32 + seg * 8;
        uint32_t dst = (uint32_t)(chunk * 8192 + r * 64
                                  + ((seg ^ ((r >> 1) & 3)) * 16));
        cp_async16(sb + RC_SB_BHI + dst, Whi + (size_t)(bn0 + r) * HH + col);
        cp_async16(sb + RC_SB_BLO + dst, Wlo + (size_t)(bn0 + r) * HH + col);
    }
    CP_COMMIT();
    CP_WAIT0();

    // Prologue: split h0 into bf16 hi/lo state buffers
    for (int i = bid * REC_THREADS + tid; i < 2 * BB * HH;
         i += REC_BLOCKS * REC_THREADS) {
        float v = h0_layer[i];
        __nv_bfloat16 hi = __float2bfloat16(v);
        g_hhi[i] = hi;
        g_hlo[i] = __float2bfloat16(v - __bfloat162float(hi));
    }

    // Per-thread gate state + step-invariant operands, hoisted for all 256 steps
    float2 hreg[2];
    int pP[2][4];          // packed (d2<<20 | b<<12 | jp) not needed; keep fields
    const float* Pp0[2]; const float* Pp1[2]; const float* Pp2[2];
    float2 brv[2], bzv[2], bnv[2];
    int pd2[2], pb[2], pjp[2], pi[2];
    int pcnt = 0;
    {
        int p = bid * REC_THREADS + tid;
#pragma unroll
        for (int q = 0; q < 2; q++) {
            if (p < 65536) {
                const int d2 = p >> 15;
                const int rm = p & 32767;
                const int b  = rm >> 9;
                const int jp = (rm & 511) << 1;
                const int i  = d2 * BB * HH + b * HH + jp;
                pd2[pcnt] = d2; pb[pcnt] = b; pjp[pcnt] = jp; pi[pcnt] = i;
                hreg[pcnt] = *(const float2*)(h0_layer + i);
                Pp0[pcnt] = g_ghp[0][d2] + (size_t)b * IN3H + jp;
                Pp1[pcnt] = g_ghp[1][d2] + (size_t)b * IN3H + jp;
                Pp2[pcnt] = g_ghp[2][d2] + (size_t)b * IN3H + jp;
                const float* bias2 = bhh_layer + d2 * IN3H + jp;
                brv[pcnt] = *(const float2*)(bias2);
                bzv[pcnt] = *(const float2*)(bias2 + HH);
                bnv[pcnt] = *(const float2*)(bias2 + 2 * HH);
                pcnt++;
            }
            p += REC_BLOCKS * REC_THREADS;
        }
        (void)pP;
    }
    grid_sync(ncalls);

    // A ldmatrix (64B swizzled rows): warp m = (wid&1)*32
    const uint32_t key   = (uint32_t)(((lid & 7) >> 1) & 3);
    const uint32_t abase = (uint32_t)(((wid & 1) * 32 + (lid & 7)
                                       + ((lid >> 3) & 1) * 8) * 64);
    const uint32_t ach   = (uint32_t)((lid >> 4) & 1);
    // B ldmatrix (64B rows, XOR swizzle): warp n = (wid>>1)*32
    const int brow0 = (wid >> 1) * 32 + (lid & 7) + ((lid >> 4) & 1) * 8;
    const int bkey  = (brow0 >> 1) & 3;
    const int lb3   = (lid >> 3) & 1;
    const uint32_t bseg0 = (uint32_t)(((0 + lb3) ^ bkey) * 16);
    const uint32_t bseg1 = (uint32_t)(((2 + lb3) ^ bkey) * 16);
    const uint32_t bbase = (uint32_t)(brow0 * 64);

    const __nv_bfloat16* hhi = g_hhi + (size_t)d * BB * HH;
    const __nv_bfloat16* hlo = g_hlo + (size_t)d * BB * HH;

    for (int s = 0; s < TT; s++) {
        float acc[2][4][4];
#pragma unroll
        for (int i = 0; i < 2; i++)
#pragma unroll
            for (int j = 0; j < 4; j++)
#pragma unroll
                for (int q = 0; q < 4; q++) acc[i][j][q] = 0.f;

        rec_loadA(sb,        hhi, hlo, kbeg,      tid); CP_COMMIT();
        rec_loadA(sb + 8192, hhi, hlo, kbeg + 32, tid); CP_COMMIT();

        // Prefetch this step's gx rows into L2 (R11 win)
        {
            const int ln = bid * REC_THREADS + tid;
            if (ln < 6144) {
                prefetch_l2(g_gx + (size_t)s * BB * IN3H + (size_t)ln * 32);
            } else if (ln < 12288) {
                prefetch_l2(g_gx + GXSZ + (size_t)(TT - 1 - s) * BB * IN3H
                            + (size_t)(ln - 6144) * 32);
            }
        }

        for (int c = 0; c < nc; c++) {
            if (c + 1 < nc) { CP_WAIT1(); } else { CP_WAIT0(); }
            __syncthreads();
            if (c + 2 < nc) {
                rec_loadA(sb + ((c + 2) % 3) * 8192, hhi, hlo,
                          kbeg + (c + 2) * 32, tid);
                CP_COMMIT();
            }
            const uint32_t stA  = sb + (c % 3) * 8192;
            const uint32_t stBh = sb + RC_SB_BHI + c * 8192 + bbase;
            const uint32_t stBl = sb + RC_SB_BLO + c * 8192 + bbase;

#pragma unroll
            for (int kk = 0; kk < 2; kk++) {
                const uint32_t ak  = ((kk * 2 + ach) ^ key) * 16;
                const uint32_t bso = kk ? bseg1 : bseg0;
                uint32_t ah[2][4], al[2][4], bh[2][4], bl[2][4];
                ldsm4(ah[0], stA + abase + ak);
                ldsm4(ah[1], stA + abase + 1024 + ak);
                ldsm4(al[0], stA + 4096 + abase + ak);
                ldsm4(al[1], stA + 4096 + abase + 1024 + ak);
                ldsm4(bh[0], stBh + bso);
                ldsm4(bh[1], stBh + 1024 + bso);
                ldsm4(bl[0], stBl + bso);
                ldsm4(bl[1], stBl + 1024 + bso);
#pragma unroll
                for (int mt = 0; mt < 2; mt++)
#pragma unroll
                    for (int g = 0; g < 2; g++) {
                        mma_bf16(acc[mt][2 * g],     ah[mt], bh[g][0], bh[g][1]);
                        mma_bf16(acc[mt][2 * g + 1], ah[mt], bh[g][2], bh[g][3]);
                    }
#pragma unroll
                for (int mt = 0; mt < 2; mt++)
#pragma unroll
                    for (int g = 0; g < 2; g++) {
                        mma_bf16(acc[mt][2 * g],     ah[mt], bl[g][0], bl[g][1]);
                        mma_bf16(acc[mt][2 * g + 1], ah[mt], bl[g][2], bl[g][3]);
                    }
#pragma unroll
                for (int mt = 0; mt < 2; mt++)
#pragma unroll
                    for (int g = 0; g < 2; g++) {
                        mma_bf16(acc[mt][2 * g],     al[mt], bh[g][0], bh[g][1]);
                        mma_bf16(acc[mt][2 * g + 1], al[mt], bh[g][2], bh[g][3]);
                    }
            }
        }

        // Epilogue: write 64x128 partial tile
        {
            const int lr = lid >> 2;
            const int lc = (lid & 3) * 2;
#pragma unroll
            for (int mt = 0; mt < 2; mt++) {
                const int row = (wid & 1) * 32 + mt * 16 + lr;
#pragma unroll
                for (int j = 0; j < 4; j++) {
                    const int col = bn0 + (wid >> 1) * 32 + j * 8 + lc;
                    float* c = acc[mt][j];
                    Pout[(size_t)row * IN3H + col]           = c[0];
                    Pout[(size_t)row * IN3H + col + 1]       = c[1];
                    Pout[(size_t)(row + 8) * IN3H + col]     = c[2];
                    Pout[(size_t)(row + 8) * IN3H + col + 1] = c[3];
                }
            }
        }

        grid_sync(ncalls);

        // Gate phase -- float2 vectorized; h state + invariants in registers
#pragma unroll
        for (int q2 = 0; q2 < 2; q2++) {
            if (q2 >= pcnt) break;
            const int d2 = pd2[q2];
            const int b  = pb[q2];
            const int jp = pjp[q2];
            const int i  = pi[q2];
            const int t  = d2 ? (TT - 1 - s) : s;

            const float* gxp = g_gx + (size_t)d2 * GXSZ
                               + ((size_t)t * BB + b) * IN3H + jp;

            float2 gr  = *(const float2*)(gxp);
            float2 gz  = *(const float2*)(gxp + HH);
            float2 gn  = *(const float2*)(gxp + 2 * HH);
            float2 p0r = *(const float2*)(Pp0[q2]);
            float2 p0z = *(const float2*)(Pp0[q2] + HH);
            float2 p0n = *(const float2*)(Pp0[q2] + 2 * HH);
            float2 p1r = *(const float2*)(Pp1[q2]);
            float2 p1z = *(const float2*)(Pp1[q2] + HH);
            float2 p1n = *(const float2*)(Pp1[q2] + 2 * HH);
            float2 p2r = *(const float2*)(Pp2[q2]);
            float2 p2z = *(const float2*)(Pp2[q2] + HH);
            float2 p2n = *(const float2*)(Pp2[q2] + 2 * HH);

            float hnew[2];
#pragma unroll
            for (int q = 0; q < 2; q++) {
                float ghr = (q ? p0r.y + p1r.y + p2r.y + brv[q2].y
                               : p0r.x + p1r.x + p2r.x + brv[q2].x);
                float ghz = (q ? p0z.y + p1z.y + p2z.y + bzv[q2].y
                               : p0z.x + p1z.x + p2z.x + bzv[q2].x);
                float ghn = (q ? p0n.y + p1n.y + p2n.y + bnv[q2].y
                               : p0n.x + p1n.x + p2n.x + bnv[q2].x);
                float gxr = q ? gr.y : gr.x;
                float gxz = q ? gz.y : gz.x;
                float gxn = q ? gn.y : gn.x;
                float hol = q ? hreg[q2].y : hreg[q2].x;

                float r = fsigmoid(gxr + ghr);
                float z = fsigmoid(gxz + ghz);
                float n = ftanh(gxn + r * ghn);
                hnew[q] = n + z * (hol - n);
            }

            hreg[q2] = make_float2(hnew[0], hnew[1]);

            __nv_bfloat162 h2 = __floats2bfloat162_rn(hnew[0], hnew[1]);
            float r0 = hnew[0] - __bfloat162float(__low2bfloat16(h2));
            float r1 = hnew[1] - __bfloat162float(__high2bfloat16(h2));
            __nv_bfloat162 l2v = __floats2bfloat162_rn(r0, r1);

            *(__nv_bfloat162*)(g_hhi + i) = h2;
            *(__nv_bfloat162*)(g_hlo + i) = l2v;

            if (emit_a) {
                size_t oidx = ((size_t)t * BB + b) * INK + (size_t)d2 * HH + jp;
                *(__nv_bfloat162*)(g_ahi + oidx) = h2;
                *(__nv_bfloat162*)(g_alo + oidx) = l2v;
            }

            if (s == TT - 1) *(float2*)(hn_out + i) = hreg[q2];
        }

        if (s < TT - 1) grid_sync(ncalls);
    }
}

// ---------------------------------------------------------------------------
// Launch
// ---------------------------------------------------------------------------
extern "C" void kernel_launch(void* const* d_in, const int* in_sizes, int n_in,
                              void* d_out, int out_size) {
    const float* x   = (const float*)d_in[0];  // [T, B, 2048]
    const float* h0  = (const float*)d_in[1];  // [6, B, H]
    const float* wih = (const float*)d_in[2];  // [3, 2, 3072, 2048]
    const float* whh = (const float*)d_in[3];  // [3, 2, 3072, 1024]
    const float* bih = (const float*)d_in[4];  // [3, 2, 3072]
    const float* bhh = (const float*)d_in[5];  // [3, 2, 3072]
    float* out = (float*)d_out;                // [6, B, H]

    __nv_bfloat16 *ahi, *alo, *whi, *wlo, *uhi, *ulo;
    void* ctr;
    cudaGetSymbolAddress((void**)&ahi, g_ahi);
    cudaGetSymbolAddress((void**)&alo, g_alo);
    cudaGetSymbolAddress((void**)&whi, g_whi);
    cudaGetSymbolAddress((void**)&wlo, g_wlo);
    cudaGetSymbolAddress((void**)&uhi, g_uhi);
    cudaGetSymbolAddress((void**)&ulo, g_ulo);
    cudaGetSymbolAddress(&ctr, g_bar_ctr);

    cudaFuncSetAttribute(gx_mma_kernel,
                         cudaFuncAttributeMaxDynamicSharedMemorySize, GX_SMEM);
    cudaFuncSetAttribute(gru_recurrent_kernel,
                         cudaFuncAttributeMaxDynamicSharedMemorySize, RC_SMEM);

    {   // split w_ih
        size_t n4 = (size_t)6 * IN3H * INK / 4;
        split_bf16_kernel<<<(unsigned)((n4 + 255) / 256), 256>>>(wih, whi, wlo, n4);
    }
    {   // split w_hh
        size_t n4 = (size_t)6 * IN3H * HH / 4;
        split_bf16_kernel<<<(unsigned)((n4 + 255) / 256), 256>>>(whh, uhi, ulo, n4);
    }
    {   // split x (layer-0 input)
        size_t n4 = (size_t)GX_M * INK / 4;
        split_bf16_kernel<<<(unsigned)((n4 + 255) / 256), 256>>>(x, ahi, alo, n4);
    }

    for (int l = 0; l < 3; l++) {
        gx_mma_kernel<<<dim3(IN3H / 128, GX_M / 128, 2), 256, GX_SMEM>>>(
            whi + (size_t)l * 2 * IN3H * INK,
            wlo + (size_t)l * 2 * IN3H * INK,
            bih + (size_t)l * 2 * IN3H);

        cudaMemsetAsync(ctr, 0, sizeof(unsigned));   // reset barrier counter

        gru_recurrent_kernel<<<REC_BLOCKS, REC_THREADS, RC_SMEM>>>(
            h0  + (size_t)l * 2 * BB * HH,
            uhi + (size_t)l * 2 * IN3H * HH,
            ulo + (size_t)l * 2 * IN3H * HH,
            bhh + (size_t)l * 2 * IN3H,
            out + (size_t)l * 2 * BB * HH,
            (l < 2) ? 1 : 0);
    }
}